// round 11
// baseline (speedup 1.0000x reference)
#include <cuda_runtime.h>
#include <cuda_bf16.h>
#include <stdint.h>
#include <math.h>

#define NN 20000
#define EE 640000
#define CC 128
#define EPSV 1e-5f
#define ASTRIDE 136

// -------------------- scratch (device globals; no allocation) --------------------
__device__ __align__(16) float  d_PQ[NN * 256];   // [node][0:128]=P, [128:256]=Q (20MB, L2-resident)
__device__ __align__(16) float  d_W0[NN * CC];
__device__ __align__(16) float  d_S1[NN * CC];
__device__ __align__(16) float  d_S2[NN * CC];    // first SP (stats), later real S2
__device__ __align__(16) __nv_bfloat16 d_Bh[128 * ASTRIDE];
__device__ __align__(16) __nv_bfloat16 d_Bl[128 * ASTRIDE];
__device__ int    d_src[EE];
__device__ int    d_dst[EE];
__device__ int    d_is64;
__device__ int    d_cnt[NN];      // indeg
__device__ int    d_ocnt[NN];     // outdeg
__device__ int    d_start[NN + 1];
__device__ int    d_cursor[NN];
__device__ int    d_srcs[EE];
__device__ float  d_dinv[NN];
__device__ double d_sum[CC];
__device__ double d_sumsq[CC];
__device__ float  d_bnA[CC];
__device__ float  d_bnB[CC];

// -------------------- dtype detect --------------------
__global__ void k_detect(const int* __restrict__ ei32) {
    if (threadIdx.x == 0) {
        int orv = 0;
        for (int i = 0; i < 128; i++) orv |= ei32[2 * i + 1];
        d_is64 = (orv == 0) ? 1 : 0;
    }
}

__global__ void k_zero() {
    int i = blockIdx.x * blockDim.x + threadIdx.x;
    int stride = gridDim.x * blockDim.x;
    for (int j = i; j < NN; j += stride) { d_cnt[j] = 0; d_ocnt[j] = 0; }
    if (i < CC) { d_sum[i] = 0.0; d_sumsq[i] = 0.0; }
}

__global__ void k_convert(const int* __restrict__ ei32) {
    const int is64 = d_is64;
    int i = blockIdx.x * blockDim.x + threadIdx.x;
    int stride = gridDim.x * blockDim.x;
    for (int e = i; e < EE; e += stride) {
        int s, d;
        if (is64) { s = ei32[2 * e]; d = ei32[2 * (EE + e)]; }
        else      { s = ei32[e];     d = ei32[EE + e]; }
        d_src[e] = s;
        d_dst[e] = d;
        atomicAdd(&d_cnt[d], 1);
        atomicAdd(&d_ocnt[s], 1);
    }
}

__global__ void k_dinv() {
    int i = blockIdx.x * blockDim.x + threadIdx.x;
    if (i < NN) d_dinv[i] = rsqrtf(1.0f + (float)d_cnt[i]);
}

__global__ void k_scan() {
    __shared__ int sh[1024];
    __shared__ int carry_s;
    const int tid = threadIdx.x;
    if (tid == 0) carry_s = 0;
    __syncthreads();
    for (int base = 0; base < NN; base += 1024) {
        int idx = base + tid;
        int v = (idx < NN) ? d_cnt[idx] : 0;
        sh[tid] = v;
        __syncthreads();
        for (int o = 1; o < 1024; o <<= 1) {
            int t = (tid >= o) ? sh[tid - o] : 0;
            __syncthreads();
            sh[tid] += t;
            __syncthreads();
        }
        int excl = sh[tid] - v + carry_s;
        if (idx < NN) { d_start[idx] = excl; d_cursor[idx] = excl; }
        __syncthreads();
        if (tid == 0) carry_s += sh[1023];
        __syncthreads();
    }
    if (tid == 0) d_start[NN] = carry_s;
}

__global__ void k_fill() {
    int e = blockIdx.x * blockDim.x + threadIdx.x;
    if (e < EE) {
        int d = d_dst[e];
        int pos = atomicAdd(&d_cursor[d], 1);
        d_srcs[pos] = d_src[e];
    }
}

// -------------------- W2 pre-split into padded hi/lo bf16 --------------------
__global__ void k_prepw(const float* __restrict__ W2) {
    int idx = blockIdx.x * blockDim.x + threadIdx.x;   // 16384
    int k = idx >> 7, n = idx & 127;
    float v = W2[(size_t)k * 128 + n];
    __nv_bfloat16 h = __float2bfloat16_rn(v);
    __nv_bfloat16 l = __float2bfloat16_rn(v - __bfloat162float(h));
    d_Bh[k * ASTRIDE + n] = h;
    d_Bl[k * ASTRIDE + n] = l;
}

// -------------------- PQ = x @ [W1_top | W1_bot] --------------------
__global__ __launch_bounds__(256) void k_pq(const float* __restrict__ x,
                                            const float* __restrict__ W1) {
    __shared__ __align__(16) float As[16][128];
    __shared__ __align__(16) float Bs[16][128];
    const int tid = threadIdx.x;
    const int tx = tid & 15, ty = tid >> 4;
    const int row0 = blockIdx.x * 128;
    const int half = blockIdx.y;
    const int m = tid & 127;
    const int kh = (tid >> 7) * 8;
    const int kb = tid >> 4;
    const int n0 = (tid & 15) * 8;

    float acc[8][8];
#pragma unroll
    for (int i = 0; i < 8; i++)
#pragma unroll
        for (int j = 0; j < 8; j++) acc[i][j] = 0.f;

    for (int k0 = 0; k0 < 128; k0 += 16) {
        float4 a0 = make_float4(0, 0, 0, 0), a1 = make_float4(0, 0, 0, 0);
        int rr = row0 + m;
        if (rr < NN) {
            const float4* ap = reinterpret_cast<const float4*>(x + (size_t)rr * 128 + k0 + kh);
            a0 = ap[0]; a1 = ap[1];
        }
        As[kh + 0][m] = a0.x; As[kh + 1][m] = a0.y; As[kh + 2][m] = a0.z; As[kh + 3][m] = a0.w;
        As[kh + 4][m] = a1.x; As[kh + 5][m] = a1.y; As[kh + 6][m] = a1.z; As[kh + 7][m] = a1.w;

        const float4* bp = reinterpret_cast<const float4*>(
            W1 + (size_t)(half * 128 + k0 + kb) * 128 + n0);
        float4 b0 = bp[0], b1v = bp[1];
        *reinterpret_cast<float4*>(&Bs[kb][n0]) = b0;
        *reinterpret_cast<float4*>(&Bs[kb][n0 + 4]) = b1v;
        __syncthreads();
#pragma unroll
        for (int k = 0; k < 16; k++) {
            float a[8], b[8];
            *reinterpret_cast<float4*>(a)     = *reinterpret_cast<const float4*>(&As[k][ty * 8]);
            *reinterpret_cast<float4*>(a + 4) = *reinterpret_cast<const float4*>(&As[k][ty * 8 + 4]);
            *reinterpret_cast<float4*>(b)     = *reinterpret_cast<const float4*>(&Bs[k][tx * 8]);
            *reinterpret_cast<float4*>(b + 4) = *reinterpret_cast<const float4*>(&Bs[k][tx * 8 + 4]);
#pragma unroll
            for (int i = 0; i < 8; i++)
#pragma unroll
                for (int j = 0; j < 8; j++) acc[i][j] = fmaf(a[i], b[j], acc[i][j]);
        }
        __syncthreads();
    }
#pragma unroll
    for (int i = 0; i < 8; i++) {
        int r = row0 + ty * 8 + i;
        if (r < NN) {
            float4 o0 = make_float4(acc[i][0], acc[i][1], acc[i][2], acc[i][3]);
            float4 o1 = make_float4(acc[i][4], acc[i][5], acc[i][6], acc[i][7]);
            float* dst = &d_PQ[(size_t)r * 256 + half * 128 + tx * 8];
            reinterpret_cast<float4*>(dst)[0] = o0;
            reinterpret_cast<float4*>(dst)[1] = o1;
        }
    }
}

__global__ void k_w0() {
    int j = blockIdx.x;
    int c = threadIdx.x;
    int s = d_src[j];
    int d = d_dst[j];
    float dv = d_dinv[j];
    d_W0[j * CC + c] = (d_PQ[s * 256 + c] + d_PQ[d * 256 + 128 + c]) * dv;
}

// -------------------- fused gather: S1 = sum W0[src], S2(SP) = sum P[src] -----------
__global__ void k_gatherA() {
    const int d = blockIdx.x;
    const int c = threadIdx.x;
    const int p0 = d_start[d], p1 = d_start[d + 1];
    float a0 = 0.f, a1 = 0.f, b0 = 0.f, b1 = 0.f;
    int p = p0;
    for (; p + 2 <= p1; p += 2) {
        int s0 = d_srcs[p], s1 = d_srcs[p + 1];
        a0 += d_W0[s0 * CC + c];
        a1 += d_W0[s1 * CC + c];
        b0 += d_PQ[s0 * 256 + c];
        b1 += d_PQ[s1 * 256 + c];
    }
    if (p < p1) {
        int s0 = d_srcs[p];
        a0 += d_W0[s0 * CC + c];
        b0 += d_PQ[s0 * 256 + c];
    }
    d_S1[d * CC + c] = a0 + a1;
    d_S2[d * CC + c] = b0 + b1;
}

// -------------------- second gather: S2 = sum W0[src]  --------------------
__global__ void k_gatherS2() {
    const int d = blockIdx.x;
    const int c = threadIdx.x;
    const int p0 = d_start[d], p1 = d_start[d + 1];
    float a0 = 0.f, a1 = 0.f, a2 = 0.f, a3 = 0.f;
    int p = p0;
    for (; p + 4 <= p1; p += 4) {
        a0 += d_W0[d_srcs[p] * CC + c];
        a1 += d_W0[d_srcs[p + 1] * CC + c];
        a2 += d_W0[d_srcs[p + 2] * CC + c];
        a3 += d_W0[d_srcs[p + 3] * CC + c];
    }
    for (; p < p1; p++) a0 += d_W0[d_srcs[p] * CC + c];
    d_S2[d * CC + c] = (a0 + a1) + (a2 + a3);
}

// -------------------- BN stats: node algebra + edge-row corrections (fused) ---------
__global__ void k_stats(const float* __restrict__ b1) {
    const int c = threadIdx.x;
    const int n0 = blockIdx.x * 128;
    const float b1c = b1[c];
    float s = 0.f, ss = 0.f;
    for (int i = 0; i < 128; i++) {
        int n = n0 + i;
        if (n < NN) {
            // node-level: sum over edges of naive h0+b1
            float od = (float)d_ocnt[n];
            float id = (float)d_cnt[n];
            float pv = d_PQ[n * 256 + c];
            float qv = d_PQ[n * 256 + 128 + c] + b1c;
            float sp = d_S2[n * CC + c];
            s += od * pv + id * qv;
            ss += od * pv * pv + id * qv * qv + 2.f * qv * sp;
            // edge-row correction for rows j<NN (GCN terms replace naive)
            int sN = d_src[n], dN = d_dst[n];
            float dv = d_dinv[n];
            float h0 = d_PQ[sN * 256 + c] + d_PQ[dN * 256 + 128 + c];
            float naive = h0 + b1c;
            float tru = fmaf(h0, dv * dv, fmaf(dv, d_S1[n * CC + c], b1c));
            s += tru - naive;
            ss += tru * tru - naive * naive;
        }
    }
    atomicAdd(&d_sum[c], (double)s);
    atomicAdd(&d_sumsq[c], (double)ss);
}

__global__ void k_bnfinal(const float* __restrict__ bn_g, const float* __restrict__ bn_b,
                          const float* __restrict__ b1) {
    int c = threadIdx.x;
    double mu = d_sum[c] / (double)EE;
    double var = d_sumsq[c] / (double)EE - mu * mu;
    float rstd = rsqrtf((float)var + EPSV);
    float a = bn_g[c] * rstd;
    d_bnA[c] = a;
    d_bnB[c] = fmaf(b1[c], a, fmaf(-(float)mu, a, bn_b[c]));
}

// ========== fp32 A-tile builder (for g2small only) ====
__device__ __forceinline__ void build_a_tile(
    float As[16][128], const int* ssrc, const int* sdst, const float* sdv,
    const float* sA, const float* sB, int row0, int m, int kh, int k0) {
    const int s = ssrc[m], d = sdst[m];
    const float dv = sdv[m];
    const float4* pp = reinterpret_cast<const float4*>(&d_PQ[s * 256 + k0 + kh]);
    float4 p0 = pp[0], p1 = pp[1];
    const float4* qp = reinterpret_cast<const float4*>(&d_PQ[d * 256 + 128 + k0 + kh]);
    float4 q0 = qp[0], q1 = qp[1];
    float h[8] = {p0.x + q0.x, p0.y + q0.y, p0.z + q0.z, p0.w + q0.w,
                  p1.x + q1.x, p1.y + q1.y, p1.z + q1.z, p1.w + q1.w};
    if (dv >= 0.f) {
        const float4* s1p = reinterpret_cast<const float4*>(&d_S1[(row0 + m) * CC + k0 + kh]);
        float4 t0 = s1p[0], t1 = s1p[1];
        float sv[8] = {t0.x, t0.y, t0.z, t0.w, t1.x, t1.y, t1.z, t1.w};
        float dv2 = dv * dv;
#pragma unroll
        for (int t = 0; t < 8; t++) h[t] = fmaf(h[t], dv2, dv * sv[t]);
    }
#pragma unroll
    for (int t = 0; t < 8; t++) {
        int kk = k0 + kh + t;
        As[kh + t][m] = fmaxf(fmaf(h[t], sA[kk], sB[kk]), 0.f);
    }
}

// -------------------- g2small (fp32, rows < NN only) --------------------
__global__ __launch_bounds__(256) void k_g2small(const float* __restrict__ W2) {
    __shared__ __align__(16) float As[16][128];
    __shared__ __align__(16) float Bs[16][128];
    __shared__ int ssrc[128], sdst[128];
    __shared__ float sdv[128], sA[128], sB[128];
    const int tid = threadIdx.x;
    const int tx = tid & 15, ty = tid >> 4;
    const int row0 = blockIdx.x * 128;
    const int m = tid & 127;
    const int kh = (tid >> 7) * 8;
    const int kb = tid >> 4;
    const int n0 = (tid & 15) * 8;

    if (tid < 128) {
        int rr = row0 + tid;
        ssrc[tid] = d_src[rr];
        sdst[tid] = d_dst[rr];
        sdv[tid] = (rr < NN) ? d_dinv[rr] : -1.f;
        sA[tid] = d_bnA[tid];
        sB[tid] = d_bnB[tid];
    }
    __syncthreads();

    float acc[8][8];
#pragma unroll
    for (int i = 0; i < 8; i++)
#pragma unroll
        for (int j = 0; j < 8; j++) acc[i][j] = 0.f;

    for (int k0 = 0; k0 < 128; k0 += 16) {
        build_a_tile(As, ssrc, sdst, sdv, sA, sB, row0, m, kh, k0);
        const float4* bp = reinterpret_cast<const float4*>(
            W2 + (size_t)(k0 + kb) * 128 + n0);
        float4 b0 = bp[0], b1v = bp[1];
        *reinterpret_cast<float4*>(&Bs[kb][n0]) = b0;
        *reinterpret_cast<float4*>(&Bs[kb][n0 + 4]) = b1v;
        __syncthreads();
#pragma unroll
        for (int k = 0; k < 16; k++) {
            float a[8], b[8];
            *reinterpret_cast<float4*>(a)     = *reinterpret_cast<const float4*>(&As[k][ty * 8]);
            *reinterpret_cast<float4*>(a + 4) = *reinterpret_cast<const float4*>(&As[k][ty * 8 + 4]);
            *reinterpret_cast<float4*>(b)     = *reinterpret_cast<const float4*>(&Bs[k][tx * 8]);
            *reinterpret_cast<float4*>(b + 4) = *reinterpret_cast<const float4*>(&Bs[k][tx * 8 + 4]);
#pragma unroll
            for (int i = 0; i < 8; i++)
#pragma unroll
                for (int j = 0; j < 8; j++) acc[i][j] = fmaf(a[i], b[j], acc[i][j]);
        }
        __syncthreads();
    }
#pragma unroll
    for (int i = 0; i < 8; i++) {
        int r = row0 + ty * 8 + i;
        if (r < NN) {
            float dv = d_dinv[r];
            float4 o0 = make_float4(acc[i][0] * dv, acc[i][1] * dv, acc[i][2] * dv, acc[i][3] * dv);
            float4 o1 = make_float4(acc[i][4] * dv, acc[i][5] * dv, acc[i][6] * dv, acc[i][7] * dv);
            float* dst = &d_W0[r * CC + tx * 8];
            reinterpret_cast<float4*>(dst)[0] = o0;
            reinterpret_cast<float4*>(dst)[1] = o1;
        }
    }
}

// ==================== k_final: split-bf16 mma.sync, 4 tiles per CTA ====================
__device__ __forceinline__ uint32_t su(const void* p) {
    return (uint32_t)__cvta_generic_to_shared(p);
}
__device__ __forceinline__ void split2(float v0, float v1, uint32_t& hi, uint32_t& lo) {
    __nv_bfloat16 h0 = __float2bfloat16_rn(v0), h1 = __float2bfloat16_rn(v1);
    float l0f = v0 - __bfloat162float(h0);
    float l1f = v1 - __bfloat162float(h1);
    __nv_bfloat16 l0 = __float2bfloat16_rn(l0f), l1 = __float2bfloat16_rn(l1f);
    hi = ((uint32_t)__bfloat16_as_ushort(h1) << 16) | (uint32_t)__bfloat16_as_ushort(h0);
    lo = ((uint32_t)__bfloat16_as_ushort(l1) << 16) | (uint32_t)__bfloat16_as_ushort(l0);
}

#define LDSM_X4(r0, r1, r2, r3, addr)                                              \
    asm volatile("ldmatrix.sync.aligned.m8n8.x4.shared.b16 {%0,%1,%2,%3},[%4];"    \
                 : "=r"(r0), "=r"(r1), "=r"(r2), "=r"(r3) : "r"(addr))
#define LDSM_X4T(r0, r1, r2, r3, addr)                                                  \
    asm volatile("ldmatrix.sync.aligned.m8n8.x4.trans.shared.b16 {%0,%1,%2,%3},[%4];"   \
                 : "=r"(r0), "=r"(r1), "=r"(r2), "=r"(r3) : "r"(addr))
#define MMA16816(d, a0, a1, a2, a3, b0, b1)                                             \
    asm volatile("mma.sync.aligned.m16n8k16.row.col.f32.bf16.bf16.f32 "                 \
                 "{%0,%1,%2,%3},{%4,%5,%6,%7},{%8,%9},{%0,%1,%2,%3};"                   \
                 : "+f"(d[0]), "+f"(d[1]), "+f"(d[2]), "+f"(d[3])                       \
                 : "r"(a0), "r"(a1), "r"(a2), "r"(a3), "r"(b0), "r"(b1))

__global__ __launch_bounds__(256) void k_final(const float* __restrict__ b2,
                                               const float* __restrict__ lng,
                                               const float* __restrict__ lnb,
                                               const float* __restrict__ W3,
                                               const float* __restrict__ b3,
                                               float* __restrict__ out) {
    extern __shared__ __align__(16) char dynsmem[];
    __nv_bfloat16* Ah = (__nv_bfloat16*)dynsmem;          // [128][ASTRIDE]
    __nv_bfloat16* Al = Ah + 128 * ASTRIDE;
    __nv_bfloat16* Bh = Al + 128 * ASTRIDE;               // [128 k][ASTRIDE n]
    __nv_bfloat16* Bl = Bh + 128 * ASTRIDE;

    __shared__ float sA[128], sB[128], sb2[128], slg[128], slb[128], sw3[128];
    __shared__ float redS[2][128], redSS[2][128], redD[2][128];

    const int tid = threadIdx.x;
    const int lane = tid & 31;
    const int w = tid >> 5;
    const int base = blockIdx.x * 512;

    if (tid < 128) {
        sA[tid] = d_bnA[tid];
        sB[tid] = d_bnB[tid];
        sb2[tid] = b2[tid];
        slg[tid] = lng[tid];
        slb[tid] = lnb[tid];
        sw3[tid] = W3[tid];
    }

    // ---- copy pre-split, padded B once ----
    {
        const uint4* gh = reinterpret_cast<const uint4*>(d_Bh);
        const uint4* gl = reinterpret_cast<const uint4*>(d_Bl);
        uint4* sh = reinterpret_cast<uint4*>(Bh);
        uint4* sl = reinterpret_cast<uint4*>(Bl);
        for (int i = tid; i < 2176; i += 256) {
            sh[i] = gh[i];
            sl[i] = gl[i];
        }
    }
    __syncthreads();

    const int rowgrp = w & 3;
    const int half = w >> 2;
    const int arow = tid >> 1;
    const int kh = (tid & 1) * 64;
    const int aOff0 = (rowgrp * 32 + (lane & 15)) * ASTRIDE + ((lane >> 4) << 3);
    const int aOff1 = aOff0 + 16 * ASTRIDE;
    const uint32_t aHB = su(Ah), aLB = su(Al);
    const int bRowK = (lane & 7) + (((lane >> 3) & 1) << 3);
    const int bColN = (half << 6) + ((lane >> 4) << 3);
    const uint32_t bHB = su(Bh), bLB = su(Bl);
    const int rA = rowgrp * 32 + (lane >> 2);
    const int cbase = (half << 6) + (lane & 3) * 2;
    const float inv = 1.f / 128.f;

    for (int t = 0; t < 4; t++) {
        const int row0 = base + t * 128;

        // ---- build A tile ----
        {
            const int r = row0 + arow;
            const int s = d_src[r], d = d_dst[r];
            const float dv = (r < NN) ? d_dinv[r] : -1.f;
            const float dv2 = dv * dv;
            const float4* pp = reinterpret_cast<const float4*>(&d_PQ[s * 256 + kh]);
            const float4* qp = reinterpret_cast<const float4*>(&d_PQ[d * 256 + 128 + kh]);
            const float4* s1p = reinterpret_cast<const float4*>(&d_S1[r * CC + kh]);
            uint32_t* ahp = reinterpret_cast<uint32_t*>(&Ah[arow * ASTRIDE + kh]);
            uint32_t* alp = reinterpret_cast<uint32_t*>(&Al[arow * ASTRIDE + kh]);
#pragma unroll 4
            for (int i = 0; i < 16; i++) {
                float4 p = pp[i], q = qp[i];
                float h0 = p.x + q.x, h1 = p.y + q.y, h2 = p.z + q.z, h3 = p.w + q.w;
                if (dv >= 0.f) {
                    float4 tt = s1p[i];
                    h0 = fmaf(h0, dv2, dv * tt.x);
                    h1 = fmaf(h1, dv2, dv * tt.y);
                    h2 = fmaf(h2, dv2, dv * tt.z);
                    h3 = fmaf(h3, dv2, dv * tt.w);
                }
                int c = kh + 4 * i;
                float v0 = fmaxf(fmaf(h0, sA[c + 0], sB[c + 0]), 0.f);
                float v1 = fmaxf(fmaf(h1, sA[c + 1], sB[c + 1]), 0.f);
                float v2 = fmaxf(fmaf(h2, sA[c + 2], sB[c + 2]), 0.f);
                float v3 = fmaxf(fmaf(h3, sA[c + 3], sB[c + 3]), 0.f);
                uint32_t hi0, lo0, hi1, lo1;
                split2(v0, v1, hi0, lo0);
                split2(v2, v3, hi1, lo1);
                ahp[2 * i] = hi0; ahp[2 * i + 1] = hi1;
                alp[2 * i] = lo0; alp[2 * i + 1] = lo1;
            }
        }
        __syncthreads();

        // ---- mma (4 independent accumulator chains, round-robin issue) ----
        float acc0[8][4], acc1[8][4];
#pragma unroll
        for (int i = 0; i < 8; i++)
#pragma unroll
            for (int j = 0; j < 4; j++) { acc0[i][j] = 0.f; acc1[i][j] = 0.f; }

        for (int k0 = 0; k0 < 128; k0 += 16) {
            uint32_t a0h0, a0h1, a0h2, a0h3, a0l0, a0l1, a0l2, a0l3;
            uint32_t a1h0, a1h1, a1h2, a1h3, a1l0, a1l1, a1l2, a1l3;
            LDSM_X4(a0h0, a0h1, a0h2, a0h3, aHB + 2u * (aOff0 + k0));
            LDSM_X4(a0l0, a0l1, a0l2, a0l3, aLB + 2u * (aOff0 + k0));
            LDSM_X4(a1h0, a1h1, a1h2, a1h3, aHB + 2u * (aOff1 + k0));
            LDSM_X4(a1l0, a1l1, a1l2, a1l3, aLB + 2u * (aOff1 + k0));
            const int bKOff = (bRowK + k0) * ASTRIDE + bColN;
#pragma unroll
            for (int nt2 = 0; nt2 < 4; nt2++) {
                const int n0 = nt2 * 16;
                uint32_t bh0, bh1, bh2, bh3, bl0, bl1, bl2, bl3;
                LDSM_X4T(bh0, bh1, bh2, bh3, bHB + 2u * (bKOff + n0));
                LDSM_X4T(bl0, bl1, bl2, bl3, bLB + 2u * (bKOff + n0));
                // round-robin over 4 independent accumulators; dependent distance = 4
                MMA16816(acc0[2 * nt2],     a0h0, a0h1, a0h2, a0h3, bh0, bh1);
                MMA16816(acc0[2 * nt2 + 1], a0h0, a0h1, a0h2, a0h3, bh2, bh3);
                MMA16816(acc1[2 * nt2],     a1h0, a1h1, a1h2, a1h3, bh0, bh1);
                MMA16816(acc1[2 * nt2 + 1], a1h0, a1h1, a1h2, a1h3, bh2, bh3);
                MMA16816(acc0[2 * nt2],     a0h0, a0h1, a0h2, a0h3, bl0, bl1);
                MMA16816(acc0[2 * nt2 + 1], a0h0, a0h1, a0h2, a0h3, bl2, bl3);
                MMA16816(acc1[2 * nt2],     a1h0, a1h1, a1h2, a1h3, bl0, bl1);
                MMA16816(acc1[2 * nt2 + 1], a1h0, a1h1, a1h2, a1h3, bl2, bl3);
                MMA16816(acc0[2 * nt2],     a0l0, a0l1, a0l2, a0l3, bh0, bh1);
                MMA16816(acc0[2 * nt2 + 1], a0l0, a0l1, a0l2, a0l3, bh2, bh3);
                MMA16816(acc1[2 * nt2],     a1l0, a1l1, a1l2, a1l3, bh0, bh1);
                MMA16816(acc1[2 * nt2 + 1], a1l0, a1l1, a1l2, a1l3, bh2, bh3);
            }
        }

        // ---- epilogue ----
        float rowS[4] = {0.f, 0.f, 0.f, 0.f};
        float rowSS[4] = {0.f, 0.f, 0.f, 0.f};
#pragma unroll
        for (int rb = 0; rb < 2; rb++) {
            float (*acc)[4] = rb ? acc1 : acc0;
#pragma unroll
            for (int sub = 0; sub < 2; sub++) {
                const int r = rA + rb * 16 + sub * 8;
                const int rg = row0 + r;
                float dv = 1.f, d2 = 1.f;
                const bool small = (rg < NN);
                if (small) { dv = d_dinv[rg]; d2 = dv * dv; }
                float s = 0.f, ss = 0.f;
#pragma unroll
                for (int nt = 0; nt < 8; nt++) {
                    const int c = cbase + nt * 8;
                    float2 sv = make_float2(0.f, 0.f);
                    if (small) sv = *reinterpret_cast<const float2*>(&d_S2[rg * CC + c]);
                    float v0 = fmaf(acc[nt][2 * sub + 0], d2, fmaf(dv, sv.x, sb2[c]));
                    float v1 = fmaf(acc[nt][2 * sub + 1], d2, fmaf(dv, sv.y, sb2[c + 1]));
                    acc[nt][2 * sub + 0] = v0;
                    acc[nt][2 * sub + 1] = v1;
                    s += v0 + v1;
                    ss += v0 * v0 + v1 * v1;
                }
                rowS[rb * 2 + sub] = s;
                rowSS[rb * 2 + sub] = ss;
            }
        }
#pragma unroll
        for (int o = 1; o <= 2; o <<= 1) {
#pragma unroll
            for (int i = 0; i < 4; i++) {
                rowS[i]  += __shfl_xor_sync(0xffffffffu, rowS[i],  o);
                rowSS[i] += __shfl_xor_sync(0xffffffffu, rowSS[i], o);
            }
        }
        if ((lane & 3) == 0) {
#pragma unroll
            for (int i = 0; i < 4; i++) {
                int r = rA + (i >> 1) * 16 + (i & 1) * 8;
                redS[half][r] = rowS[i];
                redSS[half][r] = rowSS[i];
            }
        }
        __syncthreads();

        float dot[4] = {0.f, 0.f, 0.f, 0.f};
#pragma unroll
        for (int rb = 0; rb < 2; rb++) {
            float (*acc)[4] = rb ? acc1 : acc0;
#pragma unroll
            for (int sub = 0; sub < 2; sub++) {
                const int r = rA + rb * 16 + sub * 8;
                float st = redS[0][r] + redS[1][r];
                float sst = redSS[0][r] + redSS[1][r];
                float mu = st * inv;
                float rstd = rsqrtf(sst * inv - mu * mu + EPSV);
                float dloc = 0.f;
#pragma unroll
                for (int nt = 0; nt < 8; nt++) {
                    const int c = cbase + nt * 8;
                    float y0 = fmaf((acc[nt][2 * sub + 0] - mu) * rstd, slg[c],     slb[c]);
                    float y1 = fmaf((acc[nt][2 * sub + 1] - mu) * rstd, slg[c + 1], slb[c + 1]);
                    dloc = fmaf(fmaxf(y0, 0.f), sw3[c],     dloc);
                    dloc = fmaf(fmaxf(y1, 0.f), sw3[c + 1], dloc);
                }
                dot[rb * 2 + sub] = dloc;
            }
        }
#pragma unroll
        for (int o = 1; o <= 2; o <<= 1)
#pragma unroll
            for (int i = 0; i < 4; i++)
                dot[i] += __shfl_xor_sync(0xffffffffu, dot[i], o);

        if ((lane & 3) == 0) {
#pragma unroll
            for (int i = 0; i < 4; i++) {
                int r = rA + (i >> 1) * 16 + (i & 1) * 8;
                redD[half][r] = dot[i];
            }
        }
        __syncthreads();
        if (half == 0 && (lane & 3) == 0) {
            const float b3v = b3[0];
#pragma unroll
            for (int i = 0; i < 4; i++) {
                int r = rA + (i >> 1) * 16 + (i & 1) * 8;
                out[row0 + r] = redD[0][r] + redD[1][r] + b3v;
            }
        }
        __syncthreads();
    }
}

// -------------------- launch --------------------
extern "C" void kernel_launch(void* const* d_in, const int* in_sizes, int n_in,
                              void* d_out, int out_size) {
    const float* x    = (const float*)d_in[0];
    const int*   ei32 = (const int*)d_in[1];
    const float* W1   = (const float*)d_in[2];
    const float* b1   = (const float*)d_in[3];
    const float* bn_g = (const float*)d_in[4];
    const float* bn_b = (const float*)d_in[5];
    const float* W2   = (const float*)d_in[6];
    const float* b2   = (const float*)d_in[7];
    const float* ln_g = (const float*)d_in[8];
    const float* ln_b = (const float*)d_in[9];
    const float* W3   = (const float*)d_in[10];
    const float* b3   = (const float*)d_in[11];
    float* out = (float*)d_out;

    const int FIN_SMEM = 4 * 128 * ASTRIDE * 2;   // 139,264 B
    cudaFuncSetAttribute(k_final, cudaFuncAttributeMaxDynamicSharedMemorySize, FIN_SMEM);

    k_zero<<<256, 256>>>();
    k_detect<<<1, 32>>>(ei32);
    k_prepw<<<64, 256>>>(W2);
    k_convert<<<1024, 256>>>(ei32);
    k_dinv<<<(NN + 255) / 256, 256>>>();
    k_scan<<<1, 1024>>>();
    k_fill<<<(EE + 255) / 256, 256>>>();
    k_pq<<<dim3((NN + 127) / 128, 2), 256>>>(x, W1);
    k_w0<<<NN, CC>>>();
    k_gatherA<<<NN, CC>>>();               // S1 + SP(S2) in one pass
    k_stats<<<(NN + 127) / 128, CC>>>(b1); // node algebra + edge corrections
    k_bnfinal<<<1, CC>>>(bn_g, bn_b, b1);
    k_g2small<<<(NN + 127) / 128, 256>>>(W2);
    k_gatherS2<<<NN, CC>>>();              // real S2 (overwrites SP)
    k_final<<<EE / 512, 256, FIN_SMEM>>>(b2, ln_g, ln_b, W3, b3, out);
}

// round 12
// speedup vs baseline: 1.0715x; 1.0715x over previous
#include <cuda_runtime.h>
#include <cuda_bf16.h>
#include <stdint.h>
#include <math.h>

#define NN 20000
#define EE 640000
#define CC 128
#define EPSV 1e-5f
#define ASTRIDE 136
#define TILEB (128 * ASTRIDE)          // bf16 elements per tile buffer

// -------------------- scratch (device globals; no allocation) --------------------
__device__ __align__(16) float  d_PQ[NN * 256];   // [node][0:128]=P, [128:256]=Q (20MB, L2-resident)
__device__ __align__(16) float  d_W0[NN * CC];
__device__ __align__(16) float  d_S1[NN * CC];
__device__ __align__(16) float  d_S2[NN * CC];    // first SP (stats), later real S2
__device__ __align__(16) __nv_bfloat16 d_Bh[TILEB];
__device__ __align__(16) __nv_bfloat16 d_Bl[TILEB];
__device__ int    d_src[EE];
__device__ int    d_dst[EE];
__device__ int    d_is64;
__device__ int    d_cnt[NN];      // indeg
__device__ int    d_ocnt[NN];     // outdeg
__device__ int    d_start[NN + 1];
__device__ int    d_cursor[NN];
__device__ int    d_srcs[EE];
__device__ float  d_dinv[NN];
__device__ double d_sum[CC];
__device__ double d_sumsq[CC];
__device__ float  d_bnA[CC];
__device__ float  d_bnB[CC];

// -------------------- dtype detect --------------------
__global__ void k_detect(const int* __restrict__ ei32) {
    if (threadIdx.x == 0) {
        int orv = 0;
        for (int i = 0; i < 128; i++) orv |= ei32[2 * i + 1];
        d_is64 = (orv == 0) ? 1 : 0;
    }
}

__global__ void k_zero() {
    int i = blockIdx.x * blockDim.x + threadIdx.x;
    int stride = gridDim.x * blockDim.x;
    for (int j = i; j < NN; j += stride) { d_cnt[j] = 0; d_ocnt[j] = 0; }
    if (i < CC) { d_sum[i] = 0.0; d_sumsq[i] = 0.0; }
}

__global__ void k_convert(const int* __restrict__ ei32) {
    const int is64 = d_is64;
    int i = blockIdx.x * blockDim.x + threadIdx.x;
    int stride = gridDim.x * blockDim.x;
    for (int e = i; e < EE; e += stride) {
        int s, d;
        if (is64) { s = ei32[2 * e]; d = ei32[2 * (EE + e)]; }
        else      { s = ei32[e];     d = ei32[EE + e]; }
        d_src[e] = s;
        d_dst[e] = d;
        atomicAdd(&d_cnt[d], 1);
        atomicAdd(&d_ocnt[s], 1);
    }
}

__global__ void k_dinv() {
    int i = blockIdx.x * blockDim.x + threadIdx.x;
    if (i < NN) d_dinv[i] = rsqrtf(1.0f + (float)d_cnt[i]);
}

__global__ void k_scan() {
    __shared__ int sh[1024];
    __shared__ int carry_s;
    const int tid = threadIdx.x;
    if (tid == 0) carry_s = 0;
    __syncthreads();
    for (int base = 0; base < NN; base += 1024) {
        int idx = base + tid;
        int v = (idx < NN) ? d_cnt[idx] : 0;
        sh[tid] = v;
        __syncthreads();
        for (int o = 1; o < 1024; o <<= 1) {
            int t = (tid >= o) ? sh[tid - o] : 0;
            __syncthreads();
            sh[tid] += t;
            __syncthreads();
        }
        int excl = sh[tid] - v + carry_s;
        if (idx < NN) { d_start[idx] = excl; d_cursor[idx] = excl; }
        __syncthreads();
        if (tid == 0) carry_s += sh[1023];
        __syncthreads();
    }
    if (tid == 0) d_start[NN] = carry_s;
}

__global__ void k_fill() {
    int e = blockIdx.x * blockDim.x + threadIdx.x;
    if (e < EE) {
        int d = d_dst[e];
        int pos = atomicAdd(&d_cursor[d], 1);
        d_srcs[pos] = d_src[e];
    }
}

// -------------------- W2 pre-split into padded hi/lo bf16 --------------------
__global__ void k_prepw(const float* __restrict__ W2) {
    int idx = blockIdx.x * blockDim.x + threadIdx.x;   // 16384
    int k = idx >> 7, n = idx & 127;
    float v = W2[(size_t)k * 128 + n];
    __nv_bfloat16 h = __float2bfloat16_rn(v);
    __nv_bfloat16 l = __float2bfloat16_rn(v - __bfloat162float(h));
    d_Bh[k * ASTRIDE + n] = h;
    d_Bl[k * ASTRIDE + n] = l;
}

// -------------------- PQ = x @ [W1_top | W1_bot] --------------------
__global__ __launch_bounds__(256) void k_pq(const float* __restrict__ x,
                                            const float* __restrict__ W1) {
    __shared__ __align__(16) float As[16][128];
    __shared__ __align__(16) float Bs[16][128];
    const int tid = threadIdx.x;
    const int tx = tid & 15, ty = tid >> 4;
    const int row0 = blockIdx.x * 128;
    const int half = blockIdx.y;
    const int m = tid & 127;
    const int kh = (tid >> 7) * 8;
    const int kb = tid >> 4;
    const int n0 = (tid & 15) * 8;

    float acc[8][8];
#pragma unroll
    for (int i = 0; i < 8; i++)
#pragma unroll
        for (int j = 0; j < 8; j++) acc[i][j] = 0.f;

    for (int k0 = 0; k0 < 128; k0 += 16) {
        float4 a0 = make_float4(0, 0, 0, 0), a1 = make_float4(0, 0, 0, 0);
        int rr = row0 + m;
        if (rr < NN) {
            const float4* ap = reinterpret_cast<const float4*>(x + (size_t)rr * 128 + k0 + kh);
            a0 = ap[0]; a1 = ap[1];
        }
        As[kh + 0][m] = a0.x; As[kh + 1][m] = a0.y; As[kh + 2][m] = a0.z; As[kh + 3][m] = a0.w;
        As[kh + 4][m] = a1.x; As[kh + 5][m] = a1.y; As[kh + 6][m] = a1.z; As[kh + 7][m] = a1.w;

        const float4* bp = reinterpret_cast<const float4*>(
            W1 + (size_t)(half * 128 + k0 + kb) * 128 + n0);
        float4 b0 = bp[0], b1v = bp[1];
        *reinterpret_cast<float4*>(&Bs[kb][n0]) = b0;
        *reinterpret_cast<float4*>(&Bs[kb][n0 + 4]) = b1v;
        __syncthreads();
#pragma unroll
        for (int k = 0; k < 16; k++) {
            float a[8], b[8];
            *reinterpret_cast<float4*>(a)     = *reinterpret_cast<const float4*>(&As[k][ty * 8]);
            *reinterpret_cast<float4*>(a + 4) = *reinterpret_cast<const float4*>(&As[k][ty * 8 + 4]);
            *reinterpret_cast<float4*>(b)     = *reinterpret_cast<const float4*>(&Bs[k][tx * 8]);
            *reinterpret_cast<float4*>(b + 4) = *reinterpret_cast<const float4*>(&Bs[k][tx * 8 + 4]);
#pragma unroll
            for (int i = 0; i < 8; i++)
#pragma unroll
                for (int j = 0; j < 8; j++) acc[i][j] = fmaf(a[i], b[j], acc[i][j]);
        }
        __syncthreads();
    }
#pragma unroll
    for (int i = 0; i < 8; i++) {
        int r = row0 + ty * 8 + i;
        if (r < NN) {
            float4 o0 = make_float4(acc[i][0], acc[i][1], acc[i][2], acc[i][3]);
            float4 o1 = make_float4(acc[i][4], acc[i][5], acc[i][6], acc[i][7]);
            float* dst = &d_PQ[(size_t)r * 256 + half * 128 + tx * 8];
            reinterpret_cast<float4*>(dst)[0] = o0;
            reinterpret_cast<float4*>(dst)[1] = o1;
        }
    }
}

__global__ void k_w0() {
    int j = blockIdx.x;
    int c = threadIdx.x;
    int s = d_src[j];
    int d = d_dst[j];
    float dv = d_dinv[j];
    d_W0[j * CC + c] = (d_PQ[s * 256 + c] + d_PQ[d * 256 + 128 + c]) * dv;
}

// -------------------- fused gather: S1 = sum W0[src], S2(SP) = sum P[src] -----------
__global__ void k_gatherA() {
    const int d = blockIdx.x;
    const int c = threadIdx.x;
    const int p0 = d_start[d], p1 = d_start[d + 1];
    float a0 = 0.f, a1 = 0.f, b0 = 0.f, b1 = 0.f;
    int p = p0;
    for (; p + 2 <= p1; p += 2) {
        int s0 = d_srcs[p], s1 = d_srcs[p + 1];
        a0 += d_W0[s0 * CC + c];
        a1 += d_W0[s1 * CC + c];
        b0 += d_PQ[s0 * 256 + c];
        b1 += d_PQ[s1 * 256 + c];
    }
    if (p < p1) {
        int s0 = d_srcs[p];
        a0 += d_W0[s0 * CC + c];
        b0 += d_PQ[s0 * 256 + c];
    }
    d_S1[d * CC + c] = a0 + a1;
    d_S2[d * CC + c] = b0 + b1;
}

// -------------------- second gather: S2 = sum W0[src]  --------------------
__global__ void k_gatherS2() {
    const int d = blockIdx.x;
    const int c = threadIdx.x;
    const int p0 = d_start[d], p1 = d_start[d + 1];
    float a0 = 0.f, a1 = 0.f, a2 = 0.f, a3 = 0.f;
    int p = p0;
    for (; p + 4 <= p1; p += 4) {
        a0 += d_W0[d_srcs[p] * CC + c];
        a1 += d_W0[d_srcs[p + 1] * CC + c];
        a2 += d_W0[d_srcs[p + 2] * CC + c];
        a3 += d_W0[d_srcs[p + 3] * CC + c];
    }
    for (; p < p1; p++) a0 += d_W0[d_srcs[p] * CC + c];
    d_S2[d * CC + c] = (a0 + a1) + (a2 + a3);
}

// -------------------- BN stats: node algebra + edge-row corrections (fused) ---------
__global__ void k_stats(const float* __restrict__ b1) {
    const int c = threadIdx.x;
    const int n0 = blockIdx.x * 128;
    const float b1c = b1[c];
    float s = 0.f, ss = 0.f;
    for (int i = 0; i < 128; i++) {
        int n = n0 + i;
        if (n < NN) {
            float od = (float)d_ocnt[n];
            float id = (float)d_cnt[n];
            float pv = d_PQ[n * 256 + c];
            float qv = d_PQ[n * 256 + 128 + c] + b1c;
            float sp = d_S2[n * CC + c];
            s += od * pv + id * qv;
            ss += od * pv * pv + id * qv * qv + 2.f * qv * sp;
            int sN = d_src[n], dN = d_dst[n];
            float dv = d_dinv[n];
            float h0 = d_PQ[sN * 256 + c] + d_PQ[dN * 256 + 128 + c];
            float naive = h0 + b1c;
            float tru = fmaf(h0, dv * dv, fmaf(dv, d_S1[n * CC + c], b1c));
            s += tru - naive;
            ss += tru * tru - naive * naive;
        }
    }
    atomicAdd(&d_sum[c], (double)s);
    atomicAdd(&d_sumsq[c], (double)ss);
}

__global__ void k_bnfinal(const float* __restrict__ bn_g, const float* __restrict__ bn_b,
                          const float* __restrict__ b1) {
    int c = threadIdx.x;
    double mu = d_sum[c] / (double)EE;
    double var = d_sumsq[c] / (double)EE - mu * mu;
    float rstd = rsqrtf((float)var + EPSV);
    float a = bn_g[c] * rstd;
    d_bnA[c] = a;
    d_bnB[c] = fmaf(b1[c], a, fmaf(-(float)mu, a, bn_b[c]));
}

// ========== fp32 A-tile builder (for g2small only) ====
__device__ __forceinline__ void build_a_tile(
    float As[16][128], const int* ssrc, const int* sdst, const float* sdv,
    const float* sA, const float* sB, int row0, int m, int kh, int k0) {
    const int s = ssrc[m], d = sdst[m];
    const float dv = sdv[m];
    const float4* pp = reinterpret_cast<const float4*>(&d_PQ[s * 256 + k0 + kh]);
    float4 p0 = pp[0], p1 = pp[1];
    const float4* qp = reinterpret_cast<const float4*>(&d_PQ[d * 256 + 128 + k0 + kh]);
    float4 q0 = qp[0], q1 = qp[1];
    float h[8] = {p0.x + q0.x, p0.y + q0.y, p0.z + q0.z, p0.w + q0.w,
                  p1.x + q1.x, p1.y + q1.y, p1.z + q1.z, p1.w + q1.w};
    if (dv >= 0.f) {
        const float4* s1p = reinterpret_cast<const float4*>(&d_S1[(row0 + m) * CC + k0 + kh]);
        float4 t0 = s1p[0], t1 = s1p[1];
        float sv[8] = {t0.x, t0.y, t0.z, t0.w, t1.x, t1.y, t1.z, t1.w};
        float dv2 = dv * dv;
#pragma unroll
        for (int t = 0; t < 8; t++) h[t] = fmaf(h[t], dv2, dv * sv[t]);
    }
#pragma unroll
    for (int t = 0; t < 8; t++) {
        int kk = k0 + kh + t;
        As[kh + t][m] = fmaxf(fmaf(h[t], sA[kk], sB[kk]), 0.f);
    }
}

// -------------------- g2small (fp32, rows < NN only) --------------------
__global__ __launch_bounds__(256) void k_g2small(const float* __restrict__ W2) {
    __shared__ __align__(16) float As[16][128];
    __shared__ __align__(16) float Bs[16][128];
    __shared__ int ssrc[128], sdst[128];
    __shared__ float sdv[128], sA[128], sB[128];
    const int tid = threadIdx.x;
    const int tx = tid & 15, ty = tid >> 4;
    const int row0 = blockIdx.x * 128;
    const int m = tid & 127;
    const int kh = (tid >> 7) * 8;
    const int kb = tid >> 4;
    const int n0 = (tid & 15) * 8;

    if (tid < 128) {
        int rr = row0 + tid;
        ssrc[tid] = d_src[rr];
        sdst[tid] = d_dst[rr];
        sdv[tid] = (rr < NN) ? d_dinv[rr] : -1.f;
        sA[tid] = d_bnA[tid];
        sB[tid] = d_bnB[tid];
    }
    __syncthreads();

    float acc[8][8];
#pragma unroll
    for (int i = 0; i < 8; i++)
#pragma unroll
        for (int j = 0; j < 8; j++) acc[i][j] = 0.f;

    for (int k0 = 0; k0 < 128; k0 += 16) {
        build_a_tile(As, ssrc, sdst, sdv, sA, sB, row0, m, kh, k0);
        const float4* bp = reinterpret_cast<const float4*>(
            W2 + (size_t)(k0 + kb) * 128 + n0);
        float4 b0 = bp[0], b1v = bp[1];
        *reinterpret_cast<float4*>(&Bs[kb][n0]) = b0;
        *reinterpret_cast<float4*>(&Bs[kb][n0 + 4]) = b1v;
        __syncthreads();
#pragma unroll
        for (int k = 0; k < 16; k++) {
            float a[8], b[8];
            *reinterpret_cast<float4*>(a)     = *reinterpret_cast<const float4*>(&As[k][ty * 8]);
            *reinterpret_cast<float4*>(a + 4) = *reinterpret_cast<const float4*>(&As[k][ty * 8 + 4]);
            *reinterpret_cast<float4*>(b)     = *reinterpret_cast<const float4*>(&Bs[k][tx * 8]);
            *reinterpret_cast<float4*>(b + 4) = *reinterpret_cast<const float4*>(&Bs[k][tx * 8 + 4]);
#pragma unroll
            for (int i = 0; i < 8; i++)
#pragma unroll
                for (int j = 0; j < 8; j++) acc[i][j] = fmaf(a[i], b[j], acc[i][j]);
        }
        __syncthreads();
    }
#pragma unroll
    for (int i = 0; i < 8; i++) {
        int r = row0 + ty * 8 + i;
        if (r < NN) {
            float dv = d_dinv[r];
            float4 o0 = make_float4(acc[i][0] * dv, acc[i][1] * dv, acc[i][2] * dv, acc[i][3] * dv);
            float4 o1 = make_float4(acc[i][4] * dv, acc[i][5] * dv, acc[i][6] * dv, acc[i][7] * dv);
            float* dst = &d_W0[r * CC + tx * 8];
            reinterpret_cast<float4*>(dst)[0] = o0;
            reinterpret_cast<float4*>(dst)[1] = o1;
        }
    }
}

// ============= k_final: producer/consumer warp-specialized split-bf16 mma ==============
__device__ __forceinline__ uint32_t su(const void* p) {
    return (uint32_t)__cvta_generic_to_shared(p);
}
__device__ __forceinline__ void split2(float v0, float v1, uint32_t& hi, uint32_t& lo) {
    __nv_bfloat16 h0 = __float2bfloat16_rn(v0), h1 = __float2bfloat16_rn(v1);
    float l0f = v0 - __bfloat162float(h0);
    float l1f = v1 - __bfloat162float(h1);
    __nv_bfloat16 l0 = __float2bfloat16_rn(l0f), l1 = __float2bfloat16_rn(l1f);
    hi = ((uint32_t)__bfloat16_as_ushort(h1) << 16) | (uint32_t)__bfloat16_as_ushort(h0);
    lo = ((uint32_t)__bfloat16_as_ushort(l1) << 16) | (uint32_t)__bfloat16_as_ushort(l0);
}

#define BARRIER() asm volatile("bar.sync 0;" ::: "memory")

#define LDSM_X4(r0, r1, r2, r3, addr)                                              \
    asm volatile("ldmatrix.sync.aligned.m8n8.x4.shared.b16 {%0,%1,%2,%3},[%4];"    \
                 : "=r"(r0), "=r"(r1), "=r"(r2), "=r"(r3) : "r"(addr))
#define LDSM_X4T(r0, r1, r2, r3, addr)                                                  \
    asm volatile("ldmatrix.sync.aligned.m8n8.x4.trans.shared.b16 {%0,%1,%2,%3},[%4];"   \
                 : "=r"(r0), "=r"(r1), "=r"(r2), "=r"(r3) : "r"(addr))
#define MMA16816(d, a0, a1, a2, a3, b0, b1)                                             \
    asm volatile("mma.sync.aligned.m16n8k16.row.col.f32.bf16.bf16.f32 "                 \
                 "{%0,%1,%2,%3},{%4,%5,%6,%7},{%8,%9},{%0,%1,%2,%3};"                   \
                 : "+f"(d[0]), "+f"(d[1]), "+f"(d[2]), "+f"(d[3])                       \
                 : "r"(a0), "r"(a1), "r"(a2), "r"(a3), "r"(b0), "r"(b1))

__global__ __launch_bounds__(256, 1) void k_final(const float* __restrict__ b2,
                                                  const float* __restrict__ lng,
                                                  const float* __restrict__ lnb,
                                                  const float* __restrict__ W3,
                                                  const float* __restrict__ b3,
                                                  float* __restrict__ out) {
    extern __shared__ __align__(16) char dynsmem[];
    __nv_bfloat16* Bh  = (__nv_bfloat16*)dynsmem;
    __nv_bfloat16* Bl  = Bh + TILEB;
    __nv_bfloat16* A0h = Bl + TILEB;     // buffer 0
    __nv_bfloat16* A0l = A0h + TILEB;
    __nv_bfloat16* A1h = A0l + TILEB;    // buffer 1
    __nv_bfloat16* A1l = A1h + TILEB;

    __shared__ float sA[128], sB[128], sb2[128], slg[128], slb[128], sw3[128];

    const int tid = threadIdx.x;
    const int lane = tid & 31;
    const int w = tid >> 5;
    const int base = blockIdx.x * 512;

    if (tid < 128) {
        sA[tid] = d_bnA[tid];
        sB[tid] = d_bnB[tid];
        sb2[tid] = b2[tid];
        slg[tid] = lng[tid];
        slb[tid] = lnb[tid];
        sw3[tid] = W3[tid];
    }
    // copy B hi/lo (all 256 threads)
    {
        const uint4* gh = reinterpret_cast<const uint4*>(d_Bh);
        const uint4* gl = reinterpret_cast<const uint4*>(d_Bl);
        uint4* sh = reinterpret_cast<uint4*>(Bh);
        uint4* sl = reinterpret_cast<uint4*>(Bl);
        for (int i = tid; i < 2176; i += 256) {
            sh[i] = gh[i];
            sl[i] = gl[i];
        }
    }
    BARRIER();   // #0: consts + B ready

    if (w < 4) {
        // ================= producers: 128 threads, one full row each =================
        const int ptid = tid;   // 0..127
        for (int t = 0; t < 4; t++) {
            __nv_bfloat16* Ah = (t & 1) ? A1h : A0h;
            __nv_bfloat16* Al = (t & 1) ? A1l : A0l;
            const int r = base + t * 128 + ptid;
            const int s = d_src[r], d = d_dst[r];
            const float dv = (r < NN) ? d_dinv[r] : -1.f;
            const float dv2 = dv * dv;
            const float4* pp = reinterpret_cast<const float4*>(&d_PQ[s * 256]);
            const float4* qp = reinterpret_cast<const float4*>(&d_PQ[d * 256 + 128]);
            const float4* s1p = reinterpret_cast<const float4*>(&d_S1[r * CC]);
            uint32_t* ahp = reinterpret_cast<uint32_t*>(&Ah[ptid * ASTRIDE]);
            uint32_t* alp = reinterpret_cast<uint32_t*>(&Al[ptid * ASTRIDE]);
#pragma unroll 8
            for (int i = 0; i < 32; i++) {
                float4 p = pp[i], q = qp[i];
                float h0 = p.x + q.x, h1 = p.y + q.y, h2 = p.z + q.z, h3 = p.w + q.w;
                if (dv >= 0.f) {
                    float4 tt = s1p[i];
                    h0 = fmaf(h0, dv2, dv * tt.x);
                    h1 = fmaf(h1, dv2, dv * tt.y);
                    h2 = fmaf(h2, dv2, dv * tt.z);
                    h3 = fmaf(h3, dv2, dv * tt.w);
                }
                int c = 4 * i;
                float v0 = fmaxf(fmaf(h0, sA[c + 0], sB[c + 0]), 0.f);
                float v1 = fmaxf(fmaf(h1, sA[c + 1], sB[c + 1]), 0.f);
                float v2 = fmaxf(fmaf(h2, sA[c + 2], sB[c + 2]), 0.f);
                float v3 = fmaxf(fmaf(h3, sA[c + 3], sB[c + 3]), 0.f);
                uint32_t hi0, lo0, hi1, lo1;
                split2(v0, v1, hi0, lo0);
                split2(v2, v3, hi1, lo1);
                ahp[2 * i] = hi0; ahp[2 * i + 1] = hi1;
                alp[2 * i] = lo0; alp[2 * i + 1] = lo1;
            }
            BARRIER();   // tile t built
        }
    } else {
        // ================= consumers: warp cw owns rows cw*32..+31, all 128 cols ======
        const int cw = w - 4;
        const int aOffBase = (cw * 32 + (lane & 15)) * ASTRIDE + ((lane >> 4) << 3);
        const int bRowK = (lane & 7) + (((lane >> 3) & 1) << 3);
        const int bColN = (lane >> 4) << 3;
        const uint32_t bHB = su(Bh), bLB = su(Bl);
        const int rbase = cw * 32 + (lane >> 2);
        const int cb = (lane & 3) * 2;
        const float inv = 1.f / 128.f;
        const float b3v = b3[0];

        for (int t = 0; t < 4; t++) {
            BARRIER();   // wait tile t built
            const int row0 = base + t * 128;
            const uint32_t aHB = su((t & 1) ? A1h : A0h);
            const uint32_t aLB = su((t & 1) ? A1l : A0l);

            float acc[2][16][4];
#pragma unroll
            for (int rb = 0; rb < 2; rb++)
#pragma unroll
                for (int i = 0; i < 16; i++)
#pragma unroll
                    for (int j = 0; j < 4; j++) acc[rb][i][j] = 0.f;

            for (int k0 = 0; k0 < 128; k0 += 16) {
                uint32_t a0h0, a0h1, a0h2, a0h3, a0l0, a0l1, a0l2, a0l3;
                uint32_t a1h0, a1h1, a1h2, a1h3, a1l0, a1l1, a1l2, a1l3;
                LDSM_X4(a0h0, a0h1, a0h2, a0h3, aHB + 2u * (aOffBase + k0));
                LDSM_X4(a0l0, a0l1, a0l2, a0l3, aLB + 2u * (aOffBase + k0));
                LDSM_X4(a1h0, a1h1, a1h2, a1h3, aHB + 2u * (aOffBase + 16 * ASTRIDE + k0));
                LDSM_X4(a1l0, a1l1, a1l2, a1l3, aLB + 2u * (aOffBase + 16 * ASTRIDE + k0));
                const int bKOff = (bRowK + k0) * ASTRIDE + bColN;
#pragma unroll
                for (int nt2 = 0; nt2 < 8; nt2++) {
                    const int n0 = nt2 * 16;
                    uint32_t bh0, bh1, bh2, bh3, bl0, bl1, bl2, bl3;
                    LDSM_X4T(bh0, bh1, bh2, bh3, bHB + 2u * (bKOff + n0));
                    LDSM_X4T(bl0, bl1, bl2, bl3, bLB + 2u * (bKOff + n0));
                    MMA16816(acc[0][2 * nt2],     a0h0, a0h1, a0h2, a0h3, bh0, bh1);
                    MMA16816(acc[0][2 * nt2 + 1], a0h0, a0h1, a0h2, a0h3, bh2, bh3);
                    MMA16816(acc[1][2 * nt2],     a1h0, a1h1, a1h2, a1h3, bh0, bh1);
                    MMA16816(acc[1][2 * nt2 + 1], a1h0, a1h1, a1h2, a1h3, bh2, bh3);
                    MMA16816(acc[0][2 * nt2],     a0h0, a0h1, a0h2, a0h3, bl0, bl1);
                    MMA16816(acc[0][2 * nt2 + 1], a0h0, a0h1, a0h2, a0h3, bl2, bl3);
                    MMA16816(acc[1][2 * nt2],     a1h0, a1h1, a1h2, a1h3, bl0, bl1);
                    MMA16816(acc[1][2 * nt2 + 1], a1h0, a1h1, a1h2, a1h3, bl2, bl3);
                    MMA16816(acc[0][2 * nt2],     a0l0, a0l1, a0l2, a0l3, bh0, bh1);
                    MMA16816(acc[0][2 * nt2 + 1], a0l0, a0l1, a0l2, a0l3, bh2, bh3);
                    MMA16816(acc[1][2 * nt2],     a1l0, a1l1, a1l2, a1l3, bh0, bh1);
                    MMA16816(acc[1][2 * nt2 + 1], a1l0, a1l1, a1l2, a1l3, bh2, bh3);
                }
            }

            // ---- epilogue (per-warp; LN reductions within 4-lane groups) ----
#pragma unroll
            for (int rb = 0; rb < 2; rb++) {
#pragma unroll
                for (int sub = 0; sub < 2; sub++) {
                    const int r = rbase + rb * 16 + sub * 8;
                    const int rg = row0 + r;
                    const bool small = (rg < NN);
                    float dv = 1.f, d2 = 1.f;
                    if (small) { dv = d_dinv[rg]; d2 = dv * dv; }
                    float s = 0.f, ss = 0.f;
#pragma unroll
                    for (int nt = 0; nt < 16; nt++) {
                        const int c = cb + nt * 8;
                        float2 sv = make_float2(0.f, 0.f);
                        if (small) sv = *reinterpret_cast<const float2*>(&d_S2[rg * CC + c]);
                        float v0 = fmaf(acc[rb][nt][2 * sub + 0], d2, fmaf(dv, sv.x, sb2[c]));
                        float v1 = fmaf(acc[rb][nt][2 * sub + 1], d2, fmaf(dv, sv.y, sb2[c + 1]));
                        acc[rb][nt][2 * sub + 0] = v0;
                        acc[rb][nt][2 * sub + 1] = v1;
                        s += v0 + v1;
                        ss += v0 * v0 + v1 * v1;
                    }
#pragma unroll
                    for (int o = 1; o <= 2; o <<= 1) {
                        s  += __shfl_xor_sync(0xffffffffu, s,  o);
                        ss += __shfl_xor_sync(0xffffffffu, ss, o);
                    }
                    float mu = s * inv;
                    float rstd = rsqrtf(ss * inv - mu * mu + EPSV);
                    float dot = 0.f;
#pragma unroll
                    for (int nt = 0; nt < 16; nt++) {
                        const int c = cb + nt * 8;
                        float y0 = fmaf((acc[rb][nt][2 * sub + 0] - mu) * rstd, slg[c],     slb[c]);
                        float y1 = fmaf((acc[rb][nt][2 * sub + 1] - mu) * rstd, slg[c + 1], slb[c + 1]);
                        dot = fmaf(fmaxf(y0, 0.f), sw3[c],     dot);
                        dot = fmaf(fmaxf(y1, 0.f), sw3[c + 1], dot);
                    }
#pragma unroll
                    for (int o = 1; o <= 2; o <<= 1)
                        dot += __shfl_xor_sync(0xffffffffu, dot, o);
                    if ((lane & 3) == 0) out[rg] = dot + b3v;
                }
            }
        }
    }
}

// -------------------- launch --------------------
extern "C" void kernel_launch(void* const* d_in, const int* in_sizes, int n_in,
                              void* d_out, int out_size) {
    const float* x    = (const float*)d_in[0];
    const int*   ei32 = (const int*)d_in[1];
    const float* W1   = (const float*)d_in[2];
    const float* b1   = (const float*)d_in[3];
    const float* bn_g = (const float*)d_in[4];
    const float* bn_b = (const float*)d_in[5];
    const float* W2   = (const float*)d_in[6];
    const float* b2   = (const float*)d_in[7];
    const float* ln_g = (const float*)d_in[8];
    const float* ln_b = (const float*)d_in[9];
    const float* W3   = (const float*)d_in[10];
    const float* b3   = (const float*)d_in[11];
    float* out = (float*)d_out;

    const int FIN_SMEM = 6 * TILEB * 2;   // 208,896 B
    cudaFuncSetAttribute(k_final, cudaFuncAttributeMaxDynamicSharedMemorySize, FIN_SMEM);

    k_zero<<<256, 256>>>();
    k_detect<<<1, 32>>>(ei32);
    k_prepw<<<64, 256>>>(W2);
    k_convert<<<1024, 256>>>(ei32);
    k_dinv<<<(NN + 255) / 256, 256>>>();
    k_scan<<<1, 1024>>>();
    k_fill<<<(EE + 255) / 256, 256>>>();
    k_pq<<<dim3((NN + 127) / 128, 2), 256>>>(x, W1);
    k_w0<<<NN, CC>>>();
    k_gatherA<<<NN, CC>>>();               // S1 + SP(S2) in one pass
    k_stats<<<(NN + 127) / 128, CC>>>(b1); // node algebra + edge corrections
    k_bnfinal<<<1, CC>>>(bn_g, bn_b, b1);
    k_g2small<<<(NN + 127) / 128, 256>>>(W2);
    k_gatherS2<<<NN, CC>>>();              // real S2 (overwrites SP)
    k_final<<<EE / 512, 256, FIN_SMEM>>>(b2, ln_g, ln_b, W3, b3, out);
}

// round 13
// speedup vs baseline: 1.1638x; 1.0862x over previous
#include <cuda_runtime.h>
#include <cuda_bf16.h>
#include <cuda_fp16.h>
#include <stdint.h>
#include <math.h>

#define NN 20000
#define EE 640000
#define CC 128
#define EPSV 1e-5f
#define ASTRIDE 136
#define TILEB (128 * ASTRIDE)          // fp16 elements per tile buffer

// -------------------- scratch (device globals; no allocation) --------------------
__device__ __align__(16) float  d_PQ[NN * 256];   // [node][0:128]=P, [128:256]=Q (20MB, L2-resident)
__device__ __align__(16) float  d_W0[NN * CC];
__device__ __align__(16) float  d_S1[NN * CC];
__device__ __align__(16) float  d_S2[NN * CC];    // first SP (stats), later real S2
__device__ __align__(16) __half d_Bf[TILEB];      // W2 fp16, padded rows
__device__ int    d_src[EE];
__device__ int    d_dst[EE];
__device__ int    d_is64;
__device__ int    d_cnt[NN];      // indeg
__device__ int    d_ocnt[NN];     // outdeg
__device__ int    d_start[NN + 1];
__device__ int    d_cursor[NN];
__device__ int    d_srcs[EE];
__device__ float  d_dinv[NN];
__device__ double d_sum[CC];
__device__ double d_sumsq[CC];
__device__ float  d_bnA[CC];
__device__ float  d_bnB[CC];

// -------------------- dtype detect --------------------
__global__ void k_detect(const int* __restrict__ ei32) {
    if (threadIdx.x == 0) {
        int orv = 0;
        for (int i = 0; i < 128; i++) orv |= ei32[2 * i + 1];
        d_is64 = (orv == 0) ? 1 : 0;
    }
}

__global__ void k_zero() {
    int i = blockIdx.x * blockDim.x + threadIdx.x;
    int stride = gridDim.x * blockDim.x;
    for (int j = i; j < NN; j += stride) { d_cnt[j] = 0; d_ocnt[j] = 0; }
    if (i < CC) { d_sum[i] = 0.0; d_sumsq[i] = 0.0; }
}

__global__ void k_convert(const int* __restrict__ ei32) {
    const int is64 = d_is64;
    int i = blockIdx.x * blockDim.x + threadIdx.x;
    int stride = gridDim.x * blockDim.x;
    for (int e = i; e < EE; e += stride) {
        int s, d;
        if (is64) { s = ei32[2 * e]; d = ei32[2 * (EE + e)]; }
        else      { s = ei32[e];     d = ei32[EE + e]; }
        d_src[e] = s;
        d_dst[e] = d;
        atomicAdd(&d_cnt[d], 1);
        atomicAdd(&d_ocnt[s], 1);
    }
}

__global__ void k_dinv() {
    int i = blockIdx.x * blockDim.x + threadIdx.x;
    if (i < NN) d_dinv[i] = rsqrtf(1.0f + (float)d_cnt[i]);
}

__global__ void k_scan() {
    __shared__ int sh[1024];
    __shared__ int carry_s;
    const int tid = threadIdx.x;
    if (tid == 0) carry_s = 0;
    __syncthreads();
    for (int base = 0; base < NN; base += 1024) {
        int idx = base + tid;
        int v = (idx < NN) ? d_cnt[idx] : 0;
        sh[tid] = v;
        __syncthreads();
        for (int o = 1; o < 1024; o <<= 1) {
            int t = (tid >= o) ? sh[tid - o] : 0;
            __syncthreads();
            sh[tid] += t;
            __syncthreads();
        }
        int excl = sh[tid] - v + carry_s;
        if (idx < NN) { d_start[idx] = excl; d_cursor[idx] = excl; }
        __syncthreads();
        if (tid == 0) carry_s += sh[1023];
        __syncthreads();
    }
    if (tid == 0) d_start[NN] = carry_s;
}

__global__ void k_fill() {
    int e = blockIdx.x * blockDim.x + threadIdx.x;
    if (e < EE) {
        int d = d_dst[e];
        int pos = atomicAdd(&d_cursor[d], 1);
        d_srcs[pos] = d_src[e];
    }
}

// -------------------- W2 fp16, padded rows --------------------
__global__ void k_prepw(const float* __restrict__ W2) {
    int idx = blockIdx.x * blockDim.x + threadIdx.x;   // 16384
    int k = idx >> 7, n = idx & 127;
    d_Bf[k * ASTRIDE + n] = __float2half_rn(W2[(size_t)k * 128 + n]);
}

// -------------------- PQ = x @ [W1_top | W1_bot] --------------------
__global__ __launch_bounds__(256) void k_pq(const float* __restrict__ x,
                                            const float* __restrict__ W1) {
    __shared__ __align__(16) float As[16][128];
    __shared__ __align__(16) float Bs[16][128];
    const int tid = threadIdx.x;
    const int tx = tid & 15, ty = tid >> 4;
    const int row0 = blockIdx.x * 128;
    const int half = blockIdx.y;
    const int m = tid & 127;
    const int kh = (tid >> 7) * 8;
    const int kb = tid >> 4;
    const int n0 = (tid & 15) * 8;

    float acc[8][8];
#pragma unroll
    for (int i = 0; i < 8; i++)
#pragma unroll
        for (int j = 0; j < 8; j++) acc[i][j] = 0.f;

    for (int k0 = 0; k0 < 128; k0 += 16) {
        float4 a0 = make_float4(0, 0, 0, 0), a1 = make_float4(0, 0, 0, 0);
        int rr = row0 + m;
        if (rr < NN) {
            const float4* ap = reinterpret_cast<const float4*>(x + (size_t)rr * 128 + k0 + kh);
            a0 = ap[0]; a1 = ap[1];
        }
        As[kh + 0][m] = a0.x; As[kh + 1][m] = a0.y; As[kh + 2][m] = a0.z; As[kh + 3][m] = a0.w;
        As[kh + 4][m] = a1.x; As[kh + 5][m] = a1.y; As[kh + 6][m] = a1.z; As[kh + 7][m] = a1.w;

        const float4* bp = reinterpret_cast<const float4*>(
            W1 + (size_t)(half * 128 + k0 + kb) * 128 + n0);
        float4 b0 = bp[0], b1v = bp[1];
        *reinterpret_cast<float4*>(&Bs[kb][n0]) = b0;
        *reinterpret_cast<float4*>(&Bs[kb][n0 + 4]) = b1v;
        __syncthreads();
#pragma unroll
        for (int k = 0; k < 16; k++) {
            float a[8], b[8];
            *reinterpret_cast<float4*>(a)     = *reinterpret_cast<const float4*>(&As[k][ty * 8]);
            *reinterpret_cast<float4*>(a + 4) = *reinterpret_cast<const float4*>(&As[k][ty * 8 + 4]);
            *reinterpret_cast<float4*>(b)     = *reinterpret_cast<const float4*>(&Bs[k][tx * 8]);
            *reinterpret_cast<float4*>(b + 4) = *reinterpret_cast<const float4*>(&Bs[k][tx * 8 + 4]);
#pragma unroll
            for (int i = 0; i < 8; i++)
#pragma unroll
                for (int j = 0; j < 8; j++) acc[i][j] = fmaf(a[i], b[j], acc[i][j]);
        }
        __syncthreads();
    }
#pragma unroll
    for (int i = 0; i < 8; i++) {
        int r = row0 + ty * 8 + i;
        if (r < NN) {
            float4 o0 = make_float4(acc[i][0], acc[i][1], acc[i][2], acc[i][3]);
            float4 o1 = make_float4(acc[i][4], acc[i][5], acc[i][6], acc[i][7]);
            float* dst = &d_PQ[(size_t)r * 256 + half * 128 + tx * 8];
            reinterpret_cast<float4*>(dst)[0] = o0;
            reinterpret_cast<float4*>(dst)[1] = o1;
        }
    }
}

__global__ void k_w0() {
    int j = blockIdx.x;
    int c = threadIdx.x;
    int s = d_src[j];
    int d = d_dst[j];
    float dv = d_dinv[j];
    d_W0[j * CC + c] = (d_PQ[s * 256 + c] + d_PQ[d * 256 + 128 + c]) * dv;
}

// -------------------- fused gather: S1 = sum W0[src], S2(SP) = sum P[src] -----------
__global__ void k_gatherA() {
    const int d = blockIdx.x;
    const int c = threadIdx.x;
    const int p0 = d_start[d], p1 = d_start[d + 1];
    float a0 = 0.f, a1 = 0.f, b0 = 0.f, b1 = 0.f;
    int p = p0;
    for (; p + 2 <= p1; p += 2) {
        int s0 = d_srcs[p], s1 = d_srcs[p + 1];
        a0 += d_W0[s0 * CC + c];
        a1 += d_W0[s1 * CC + c];
        b0 += d_PQ[s0 * 256 + c];
        b1 += d_PQ[s1 * 256 + c];
    }
    if (p < p1) {
        int s0 = d_srcs[p];
        a0 += d_W0[s0 * CC + c];
        b0 += d_PQ[s0 * 256 + c];
    }
    d_S1[d * CC + c] = a0 + a1;
    d_S2[d * CC + c] = b0 + b1;
}

// -------------------- second gather: S2 = sum W0[src]  --------------------
__global__ void k_gatherS2() {
    const int d = blockIdx.x;
    const int c = threadIdx.x;
    const int p0 = d_start[d], p1 = d_start[d + 1];
    float a0 = 0.f, a1 = 0.f, a2 = 0.f, a3 = 0.f;
    int p = p0;
    for (; p + 4 <= p1; p += 4) {
        a0 += d_W0[d_srcs[p] * CC + c];
        a1 += d_W0[d_srcs[p + 1] * CC + c];
        a2 += d_W0[d_srcs[p + 2] * CC + c];
        a3 += d_W0[d_srcs[p + 3] * CC + c];
    }
    for (; p < p1; p++) a0 += d_W0[d_srcs[p] * CC + c];
    d_S2[d * CC + c] = (a0 + a1) + (a2 + a3);
}

// -------------------- BN stats: node algebra + edge-row corrections (fused) ---------
__global__ void k_stats(const float* __restrict__ b1) {
    const int c = threadIdx.x;
    const int n0 = blockIdx.x * 128;
    const float b1c = b1[c];
    float s = 0.f, ss = 0.f;
    for (int i = 0; i < 128; i++) {
        int n = n0 + i;
        if (n < NN) {
            float od = (float)d_ocnt[n];
            float id = (float)d_cnt[n];
            float pv = d_PQ[n * 256 + c];
            float qv = d_PQ[n * 256 + 128 + c] + b1c;
            float sp = d_S2[n * CC + c];
            s += od * pv + id * qv;
            ss += od * pv * pv + id * qv * qv + 2.f * qv * sp;
            int sN = d_src[n], dN = d_dst[n];
            float dv = d_dinv[n];
            float h0 = d_PQ[sN * 256 + c] + d_PQ[dN * 256 + 128 + c];
            float naive = h0 + b1c;
            float tru = fmaf(h0, dv * dv, fmaf(dv, d_S1[n * CC + c], b1c));
            s += tru - naive;
            ss += tru * tru - naive * naive;
        }
    }
    atomicAdd(&d_sum[c], (double)s);
    atomicAdd(&d_sumsq[c], (double)ss);
}

__global__ void k_bnfinal(const float* __restrict__ bn_g, const float* __restrict__ bn_b,
                          const float* __restrict__ b1) {
    int c = threadIdx.x;
    double mu = d_sum[c] / (double)EE;
    double var = d_sumsq[c] / (double)EE - mu * mu;
    float rstd = rsqrtf((float)var + EPSV);
    float a = bn_g[c] * rstd;
    d_bnA[c] = a;
    d_bnB[c] = fmaf(b1[c], a, fmaf(-(float)mu, a, bn_b[c]));
}

// ========== fp32 A-tile builder (for g2small only) ====
__device__ __forceinline__ void build_a_tile(
    float As[16][128], const int* ssrc, const int* sdst, const float* sdv,
    const float* sA, const float* sB, int row0, int m, int kh, int k0) {
    const int s = ssrc[m], d = sdst[m];
    const float dv = sdv[m];
    const float4* pp = reinterpret_cast<const float4*>(&d_PQ[s * 256 + k0 + kh]);
    float4 p0 = pp[0], p1 = pp[1];
    const float4* qp = reinterpret_cast<const float4*>(&d_PQ[d * 256 + 128 + k0 + kh]);
    float4 q0 = qp[0], q1 = qp[1];
    float h[8] = {p0.x + q0.x, p0.y + q0.y, p0.z + q0.z, p0.w + q0.w,
                  p1.x + q1.x, p1.y + q1.y, p1.z + q1.z, p1.w + q1.w};
    if (dv >= 0.f) {
        const float4* s1p = reinterpret_cast<const float4*>(&d_S1[(row0 + m) * CC + k0 + kh]);
        float4 t0 = s1p[0], t1 = s1p[1];
        float sv[8] = {t0.x, t0.y, t0.z, t0.w, t1.x, t1.y, t1.z, t1.w};
        float dv2 = dv * dv;
#pragma unroll
        for (int t = 0; t < 8; t++) h[t] = fmaf(h[t], dv2, dv * sv[t]);
    }
#pragma unroll
    for (int t = 0; t < 8; t++) {
        int kk = k0 + kh + t;
        As[kh + t][m] = fmaxf(fmaf(h[t], sA[kk], sB[kk]), 0.f);
    }
}

// -------------------- g2small (fp32, rows < NN only) --------------------
__global__ __launch_bounds__(256) void k_g2small(const float* __restrict__ W2) {
    __shared__ __align__(16) float As[16][128];
    __shared__ __align__(16) float Bs[16][128];
    __shared__ int ssrc[128], sdst[128];
    __shared__ float sdv[128], sA[128], sB[128];
    const int tid = threadIdx.x;
    const int tx = tid & 15, ty = tid >> 4;
    const int row0 = blockIdx.x * 128;
    const int m = tid & 127;
    const int kh = (tid >> 7) * 8;
    const int kb = tid >> 4;
    const int n0 = (tid & 15) * 8;

    if (tid < 128) {
        int rr = row0 + tid;
        ssrc[tid] = d_src[rr];
        sdst[tid] = d_dst[rr];
        sdv[tid] = (rr < NN) ? d_dinv[rr] : -1.f;
        sA[tid] = d_bnA[tid];
        sB[tid] = d_bnB[tid];
    }
    __syncthreads();

    float acc[8][8];
#pragma unroll
    for (int i = 0; i < 8; i++)
#pragma unroll
        for (int j = 0; j < 8; j++) acc[i][j] = 0.f;

    for (int k0 = 0; k0 < 128; k0 += 16) {
        build_a_tile(As, ssrc, sdst, sdv, sA, sB, row0, m, kh, k0);
        const float4* bp = reinterpret_cast<const float4*>(
            W2 + (size_t)(k0 + kb) * 128 + n0);
        float4 b0 = bp[0], b1v = bp[1];
        *reinterpret_cast<float4*>(&Bs[kb][n0]) = b0;
        *reinterpret_cast<float4*>(&Bs[kb][n0 + 4]) = b1v;
        __syncthreads();
#pragma unroll
        for (int k = 0; k < 16; k++) {
            float a[8], b[8];
            *reinterpret_cast<float4*>(a)     = *reinterpret_cast<const float4*>(&As[k][ty * 8]);
            *reinterpret_cast<float4*>(a + 4) = *reinterpret_cast<const float4*>(&As[k][ty * 8 + 4]);
            *reinterpret_cast<float4*>(b)     = *reinterpret_cast<const float4*>(&Bs[k][tx * 8]);
            *reinterpret_cast<float4*>(b + 4) = *reinterpret_cast<const float4*>(&Bs[k][tx * 8 + 4]);
#pragma unroll
            for (int i = 0; i < 8; i++)
#pragma unroll
                for (int j = 0; j < 8; j++) acc[i][j] = fmaf(a[i], b[j], acc[i][j]);
        }
        __syncthreads();
    }
#pragma unroll
    for (int i = 0; i < 8; i++) {
        int r = row0 + ty * 8 + i;
        if (r < NN) {
            float dv = d_dinv[r];
            float4 o0 = make_float4(acc[i][0] * dv, acc[i][1] * dv, acc[i][2] * dv, acc[i][3] * dv);
            float4 o1 = make_float4(acc[i][4] * dv, acc[i][5] * dv, acc[i][6] * dv, acc[i][7] * dv);
            float* dst = &d_W0[r * CC + tx * 8];
            reinterpret_cast<float4*>(dst)[0] = o0;
            reinterpret_cast<float4*>(dst)[1] = o1;
        }
    }
}

// ====== k_final: producer/consumer, fp16 A-split (hi/lo) x fp16 B, mma.sync ==========
__device__ __forceinline__ uint32_t su(const void* p) {
    return (uint32_t)__cvta_generic_to_shared(p);
}
__device__ __forceinline__ void split2h(float v0, float v1, uint32_t& hi, uint32_t& lo) {
    __half h0 = __float2half_rn(v0), h1 = __float2half_rn(v1);
    __half l0 = __float2half_rn(v0 - __half2float(h0));
    __half l1 = __float2half_rn(v1 - __half2float(h1));
    hi = ((uint32_t)__half_as_ushort(h1) << 16) | (uint32_t)__half_as_ushort(h0);
    lo = ((uint32_t)__half_as_ushort(l1) << 16) | (uint32_t)__half_as_ushort(l0);
}

#define BARRIER() asm volatile("bar.sync 0;" ::: "memory")

#define LDSM_X4(r0, r1, r2, r3, addr)                                              \
    asm volatile("ldmatrix.sync.aligned.m8n8.x4.shared.b16 {%0,%1,%2,%3},[%4];"    \
                 : "=r"(r0), "=r"(r1), "=r"(r2), "=r"(r3) : "r"(addr))
#define LDSM_X4T(r0, r1, r2, r3, addr)                                                  \
    asm volatile("ldmatrix.sync.aligned.m8n8.x4.trans.shared.b16 {%0,%1,%2,%3},[%4];"   \
                 : "=r"(r0), "=r"(r1), "=r"(r2), "=r"(r3) : "r"(addr))
#define MMAF16(d, a0, a1, a2, a3, b0, b1)                                               \
    asm volatile("mma.sync.aligned.m16n8k16.row.col.f32.f16.f16.f32 "                   \
                 "{%0,%1,%2,%3},{%4,%5,%6,%7},{%8,%9},{%0,%1,%2,%3};"                   \
                 : "+f"(d[0]), "+f"(d[1]), "+f"(d[2]), "+f"(d[3])                       \
                 : "r"(a0), "r"(a1), "r"(a2), "r"(a3), "r"(b0), "r"(b1))

__global__ __launch_bounds__(256, 1) void k_final(const float* __restrict__ b2,
                                                  const float* __restrict__ lng,
                                                  const float* __restrict__ lnb,
                                                  const float* __restrict__ W3,
                                                  const float* __restrict__ b3,
                                                  float* __restrict__ out) {
    extern __shared__ __align__(16) char dynsmem[];
    __half* Bf  = (__half*)dynsmem;
    __half* A0h = Bf + TILEB;            // buffer 0
    __half* A0l = A0h + TILEB;
    __half* A1h = A0l + TILEB;           // buffer 1
    __half* A1l = A1h + TILEB;

    __shared__ float sA[128], sB[128], sb2[128], slg[128], slb[128], sw3[128];

    const int tid = threadIdx.x;
    const int lane = tid & 31;
    const int w = tid >> 5;
    const int base = blockIdx.x * 512;

    if (tid < 128) {
        sA[tid] = d_bnA[tid];
        sB[tid] = d_bnB[tid];
        sb2[tid] = b2[tid];
        slg[tid] = lng[tid];
        slb[tid] = lnb[tid];
        sw3[tid] = W3[tid];
    }
    // copy B fp16 (34,816 B)
    {
        const uint4* gb = reinterpret_cast<const uint4*>(d_Bf);
        uint4* sb = reinterpret_cast<uint4*>(Bf);
        for (int i = tid; i < 2176; i += 256) sb[i] = gb[i];
    }
    BARRIER();   // #0: consts + B ready

    if (w < 4) {
        // ================= producers: 128 threads, one full row each =================
        const int ptid = tid;   // 0..127
        for (int t = 0; t < 4; t++) {
            __half* Ah = (t & 1) ? A1h : A0h;
            __half* Al = (t & 1) ? A1l : A0l;
            const int r = base + t * 128 + ptid;
            const int s = d_src[r], d = d_dst[r];
            const float dv = (r < NN) ? d_dinv[r] : -1.f;
            const float dv2 = dv * dv;
            const float4* pp = reinterpret_cast<const float4*>(&d_PQ[s * 256]);
            const float4* qp = reinterpret_cast<const float4*>(&d_PQ[d * 256 + 128]);
            const float4* s1p = reinterpret_cast<const float4*>(&d_S1[r * CC]);
            uint32_t* ahp = reinterpret_cast<uint32_t*>(&Ah[ptid * ASTRIDE]);
            uint32_t* alp = reinterpret_cast<uint32_t*>(&Al[ptid * ASTRIDE]);
#pragma unroll 8
            for (int i = 0; i < 32; i++) {
                float4 p = pp[i], q = qp[i];
                float h0 = p.x + q.x, h1 = p.y + q.y, h2 = p.z + q.z, h3 = p.w + q.w;
                if (dv >= 0.f) {
                    float4 tt = s1p[i];
                    h0 = fmaf(h0, dv2, dv * tt.x);
                    h1 = fmaf(h1, dv2, dv * tt.y);
                    h2 = fmaf(h2, dv2, dv * tt.z);
                    h3 = fmaf(h3, dv2, dv * tt.w);
                }
                int c = 4 * i;
                float v0 = fmaxf(fmaf(h0, sA[c + 0], sB[c + 0]), 0.f);
                float v1 = fmaxf(fmaf(h1, sA[c + 1], sB[c + 1]), 0.f);
                float v2 = fmaxf(fmaf(h2, sA[c + 2], sB[c + 2]), 0.f);
                float v3 = fmaxf(fmaf(h3, sA[c + 3], sB[c + 3]), 0.f);
                uint32_t hi0, lo0, hi1, lo1;
                split2h(v0, v1, hi0, lo0);
                split2h(v2, v3, hi1, lo1);
                ahp[2 * i] = hi0; ahp[2 * i + 1] = hi1;
                alp[2 * i] = lo0; alp[2 * i + 1] = lo1;
            }
            BARRIER();   // tile t built
        }
    } else {
        // ================= consumers: warp cw owns rows cw*32..+31, all 128 cols ======
        const int cw = w - 4;
        const int aOffBase = (cw * 32 + (lane & 15)) * ASTRIDE + ((lane >> 4) << 3);
        const int bRowK = (lane & 7) + (((lane >> 3) & 1) << 3);
        const int bColN = (lane >> 4) << 3;
        const uint32_t bFB = su(Bf);
        const int rbase = cw * 32 + (lane >> 2);
        const int cb = (lane & 3) * 2;
        const float inv = 1.f / 128.f;
        const float b3v = b3[0];

        for (int t = 0; t < 4; t++) {
            BARRIER();   // wait tile t built
            const int row0 = base + t * 128;
            const uint32_t aHB = su((t & 1) ? A1h : A0h);
            const uint32_t aLB = su((t & 1) ? A1l : A0l);

            float acc[2][16][4];
#pragma unroll
            for (int rb = 0; rb < 2; rb++)
#pragma unroll
                for (int i = 0; i < 16; i++)
#pragma unroll
                    for (int j = 0; j < 4; j++) acc[rb][i][j] = 0.f;

            for (int k0 = 0; k0 < 128; k0 += 16) {
                uint32_t a0h0, a0h1, a0h2, a0h3, a0l0, a0l1, a0l2, a0l3;
                uint32_t a1h0, a1h1, a1h2, a1h3, a1l0, a1l1, a1l2, a1l3;
                LDSM_X4(a0h0, a0h1, a0h2, a0h3, aHB + 2u * (aOffBase + k0));
                LDSM_X4(a0l0, a0l1, a0l2, a0l3, aLB + 2u * (aOffBase + k0));
                LDSM_X4(a1h0, a1h1, a1h2, a1h3, aHB + 2u * (aOffBase + 16 * ASTRIDE + k0));
                LDSM_X4(a1l0, a1l1, a1l2, a1l3, aLB + 2u * (aOffBase + 16 * ASTRIDE + k0));
                const int bKOff = (bRowK + k0) * ASTRIDE + bColN;
#pragma unroll
                for (int nt2 = 0; nt2 < 8; nt2++) {
                    const int n0 = nt2 * 16;
                    uint32_t bf0, bf1, bf2, bf3;
                    LDSM_X4T(bf0, bf1, bf2, bf3, bFB + 2u * (bKOff + n0));
                    MMAF16(acc[0][2 * nt2],     a0h0, a0h1, a0h2, a0h3, bf0, bf1);
                    MMAF16(acc[0][2 * nt2 + 1], a0h0, a0h1, a0h2, a0h3, bf2, bf3);
                    MMAF16(acc[1][2 * nt2],     a1h0, a1h1, a1h2, a1h3, bf0, bf1);
                    MMAF16(acc[1][2 * nt2 + 1], a1h0, a1h1, a1h2, a1h3, bf2, bf3);
                    MMAF16(acc[0][2 * nt2],     a0l0, a0l1, a0l2, a0l3, bf0, bf1);
                    MMAF16(acc[0][2 * nt2 + 1], a0l0, a0l1, a0l2, a0l3, bf2, bf3);
                    MMAF16(acc[1][2 * nt2],     a1l0, a1l1, a1l2, a1l3, bf0, bf1);
                    MMAF16(acc[1][2 * nt2 + 1], a1l0, a1l1, a1l2, a1l3, bf2, bf3);
                }
            }

            // ---- epilogue (per-warp; LN reductions within 4-lane groups) ----
#pragma unroll
            for (int rb = 0; rb < 2; rb++) {
#pragma unroll
                for (int sub = 0; sub < 2; sub++) {
                    const int r = rbase + rb * 16 + sub * 8;
                    const int rg = row0 + r;
                    const bool small = (rg < NN);
                    float dv = 1.f, d2 = 1.f;
                    if (small) { dv = d_dinv[rg]; d2 = dv * dv; }
                    float s = 0.f, ss = 0.f;
#pragma unroll
                    for (int nt = 0; nt < 16; nt++) {
                        const int c = cb + nt * 8;
                        float2 sv = make_float2(0.f, 0.f);
                        if (small) sv = *reinterpret_cast<const float2*>(&d_S2[rg * CC + c]);
                        float v0 = fmaf(acc[rb][nt][2 * sub + 0], d2, fmaf(dv, sv.x, sb2[c]));
                        float v1 = fmaf(acc[rb][nt][2 * sub + 1], d2, fmaf(dv, sv.y, sb2[c + 1]));
                        acc[rb][nt][2 * sub + 0] = v0;
                        acc[rb][nt][2 * sub + 1] = v1;
                        s += v0 + v1;
                        ss += v0 * v0 + v1 * v1;
                    }
#pragma unroll
                    for (int o = 1; o <= 2; o <<= 1) {
                        s  += __shfl_xor_sync(0xffffffffu, s,  o);
                        ss += __shfl_xor_sync(0xffffffffu, ss, o);
                    }
                    float mu = s * inv;
                    float rstd = rsqrtf(ss * inv - mu * mu + EPSV);
                    float dot = 0.f;
#pragma unroll
                    for (int nt = 0; nt < 16; nt++) {
                        const int c = cb + nt * 8;
                        float y0 = fmaf((acc[rb][nt][2 * sub + 0] - mu) * rstd, slg[c],     slb[c]);
                        float y1 = fmaf((acc[rb][nt][2 * sub + 1] - mu) * rstd, slg[c + 1], slb[c + 1]);
                        dot = fmaf(fmaxf(y0, 0.f), sw3[c],     dot);
                        dot = fmaf(fmaxf(y1, 0.f), sw3[c + 1], dot);
                    }
#pragma unroll
                    for (int o = 1; o <= 2; o <<= 1)
                        dot += __shfl_xor_sync(0xffffffffu, dot, o);
                    if ((lane & 3) == 0) out[rg] = dot + b3v;
                }
            }
        }
    }
}

// -------------------- launch --------------------
extern "C" void kernel_launch(void* const* d_in, const int* in_sizes, int n_in,
                              void* d_out, int out_size) {
    const float* x    = (const float*)d_in[0];
    const int*   ei32 = (const int*)d_in[1];
    const float* W1   = (const float*)d_in[2];
    const float* b1   = (const float*)d_in[3];
    const float* bn_g = (const float*)d_in[4];
    const float* bn_b = (const float*)d_in[5];
    const float* W2   = (const float*)d_in[6];
    const float* b2   = (const float*)d_in[7];
    const float* ln_g = (const float*)d_in[8];
    const float* ln_b = (const float*)d_in[9];
    const float* W3   = (const float*)d_in[10];
    const float* b3   = (const float*)d_in[11];
    float* out = (float*)d_out;

    const int FIN_SMEM = 5 * TILEB * 2;   // 174,080 B
    cudaFuncSetAttribute(k_final, cudaFuncAttributeMaxDynamicSharedMemorySize, FIN_SMEM);

    k_zero<<<256, 256>>>();
    k_detect<<<1, 32>>>(ei32);
    k_prepw<<<64, 256>>>(W2);
    k_convert<<<1024, 256>>>(ei32);
    k_dinv<<<(NN + 255) / 256, 256>>>();
    k_scan<<<1, 1024>>>();
    k_fill<<<(EE + 255) / 256, 256>>>();
    k_pq<<<dim3((NN + 127) / 128, 2), 256>>>(x, W1);
    k_w0<<<NN, CC>>>();
    k_gatherA<<<NN, CC>>>();               // S1 + SP(S2) in one pass
    k_stats<<<(NN + 127) / 128, CC>>>(b1); // node algebra + edge corrections
    k_bnfinal<<<1, CC>>>(bn_g, bn_b, b1);
    k_g2small<<<(NN + 127) / 128, 256>>>(W2);
    k_gatherS2<<<NN, CC>>>();              // real S2 (overwrites SP)
    k_final<<<EE / 512, 256, FIN_SMEM>>>(b2, ln_g, ln_b, W3, b3, out);
}

// round 14
// speedup vs baseline: 1.1735x; 1.0084x over previous
#include <cuda_runtime.h>
#include <cuda_bf16.h>
#include <cuda_fp16.h>
#include <stdint.h>
#include <math.h>

#define NN 20000
#define EE 640000
#define CC 128
#define EPSV 1e-5f
#define ASTRIDE 136
#define TILEB (128 * ASTRIDE)          // fp16 elements per tile buffer

// -------------------- scratch (device globals; no allocation) --------------------
__device__ __align__(16) float  d_PQ[NN * 256];   // [node][0:128]=P, [128:256]=Q (20MB, L2-resident)
__device__ __align__(16) float  d_W0[NN * CC];
__device__ __align__(16) float  d_S1[NN * CC];
__device__ __align__(16) float  d_S2[NN * CC];    // first SP (stats), later real S2
__device__ __align__(16) __half d_Bf[TILEB];      // W2 fp16, padded rows
__device__ int    d_src[EE];
__device__ int    d_dst[EE];
__device__ int    d_is64;
__device__ int    d_cnt[NN];      // indeg
__device__ int    d_ocnt[NN];     // outdeg
__device__ int    d_start[NN + 1];
__device__ int    d_cursor[NN];
__device__ int    d_srcs[EE];
__device__ float  d_dinv[NN];
__device__ double d_sum[CC];
__device__ double d_sumsq[CC];
__device__ float  d_bnA[CC];
__device__ float  d_bnB[CC];

// -------------------- dtype detect --------------------
__global__ void k_detect(const int* __restrict__ ei32) {
    if (threadIdx.x == 0) {
        int orv = 0;
        for (int i = 0; i < 128; i++) orv |= ei32[2 * i + 1];
        d_is64 = (orv == 0) ? 1 : 0;
    }
}

__global__ void k_zero() {
    int i = blockIdx.x * blockDim.x + threadIdx.x;
    int stride = gridDim.x * blockDim.x;
    for (int j = i; j < NN; j += stride) { d_cnt[j] = 0; d_ocnt[j] = 0; }
    if (i < CC) { d_sum[i] = 0.0; d_sumsq[i] = 0.0; }
}

__global__ void k_convert(const int* __restrict__ ei32) {
    const int is64 = d_is64;
    int i = blockIdx.x * blockDim.x + threadIdx.x;
    int stride = gridDim.x * blockDim.x;
    for (int e = i; e < EE; e += stride) {
        int s, d;
        if (is64) { s = ei32[2 * e]; d = ei32[2 * (EE + e)]; }
        else      { s = ei32[e];     d = ei32[EE + e]; }
        d_src[e] = s;
        d_dst[e] = d;
        atomicAdd(&d_cnt[d], 1);
        atomicAdd(&d_ocnt[s], 1);
    }
}

__global__ void k_dinv() {
    int i = blockIdx.x * blockDim.x + threadIdx.x;
    if (i < NN) d_dinv[i] = rsqrtf(1.0f + (float)d_cnt[i]);
}

__global__ void k_scan() {
    __shared__ int sh[1024];
    __shared__ int carry_s;
    const int tid = threadIdx.x;
    if (tid == 0) carry_s = 0;
    __syncthreads();
    for (int base = 0; base < NN; base += 1024) {
        int idx = base + tid;
        int v = (idx < NN) ? d_cnt[idx] : 0;
        sh[tid] = v;
        __syncthreads();
        for (int o = 1; o < 1024; o <<= 1) {
            int t = (tid >= o) ? sh[tid - o] : 0;
            __syncthreads();
            sh[tid] += t;
            __syncthreads();
        }
        int excl = sh[tid] - v + carry_s;
        if (idx < NN) { d_start[idx] = excl; d_cursor[idx] = excl; }
        __syncthreads();
        if (tid == 0) carry_s += sh[1023];
        __syncthreads();
    }
    if (tid == 0) d_start[NN] = carry_s;
}

__global__ void k_fill() {
    int e = blockIdx.x * blockDim.x + threadIdx.x;
    if (e < EE) {
        int d = d_dst[e];
        int pos = atomicAdd(&d_cursor[d], 1);
        d_srcs[pos] = d_src[e];
    }
}

// -------------------- W2 fp16, padded rows --------------------
__global__ void k_prepw(const float* __restrict__ W2) {
    int idx = blockIdx.x * blockDim.x + threadIdx.x;   // 16384
    int k = idx >> 7, n = idx & 127;
    d_Bf[k * ASTRIDE + n] = __float2half_rn(W2[(size_t)k * 128 + n]);
}

// -------------------- PQ = x @ [W1_top | W1_bot] --------------------
__global__ __launch_bounds__(256) void k_pq(const float* __restrict__ x,
                                            const float* __restrict__ W1) {
    __shared__ __align__(16) float As[16][128];
    __shared__ __align__(16) float Bs[16][128];
    const int tid = threadIdx.x;
    const int tx = tid & 15, ty = tid >> 4;
    const int row0 = blockIdx.x * 128;
    const int half = blockIdx.y;
    const int m = tid & 127;
    const int kh = (tid >> 7) * 8;
    const int kb = tid >> 4;
    const int n0 = (tid & 15) * 8;

    float acc[8][8];
#pragma unroll
    for (int i = 0; i < 8; i++)
#pragma unroll
        for (int j = 0; j < 8; j++) acc[i][j] = 0.f;

    for (int k0 = 0; k0 < 128; k0 += 16) {
        float4 a0 = make_float4(0, 0, 0, 0), a1 = make_float4(0, 0, 0, 0);
        int rr = row0 + m;
        if (rr < NN) {
            const float4* ap = reinterpret_cast<const float4*>(x + (size_t)rr * 128 + k0 + kh);
            a0 = ap[0]; a1 = ap[1];
        }
        As[kh + 0][m] = a0.x; As[kh + 1][m] = a0.y; As[kh + 2][m] = a0.z; As[kh + 3][m] = a0.w;
        As[kh + 4][m] = a1.x; As[kh + 5][m] = a1.y; As[kh + 6][m] = a1.z; As[kh + 7][m] = a1.w;

        const float4* bp = reinterpret_cast<const float4*>(
            W1 + (size_t)(half * 128 + k0 + kb) * 128 + n0);
        float4 b0 = bp[0], b1v = bp[1];
        *reinterpret_cast<float4*>(&Bs[kb][n0]) = b0;
        *reinterpret_cast<float4*>(&Bs[kb][n0 + 4]) = b1v;
        __syncthreads();
#pragma unroll
        for (int k = 0; k < 16; k++) {
            float a[8], b[8];
            *reinterpret_cast<float4*>(a)     = *reinterpret_cast<const float4*>(&As[k][ty * 8]);
            *reinterpret_cast<float4*>(a + 4) = *reinterpret_cast<const float4*>(&As[k][ty * 8 + 4]);
            *reinterpret_cast<float4*>(b)     = *reinterpret_cast<const float4*>(&Bs[k][tx * 8]);
            *reinterpret_cast<float4*>(b + 4) = *reinterpret_cast<const float4*>(&Bs[k][tx * 8 + 4]);
#pragma unroll
            for (int i = 0; i < 8; i++)
#pragma unroll
                for (int j = 0; j < 8; j++) acc[i][j] = fmaf(a[i], b[j], acc[i][j]);
        }
        __syncthreads();
    }
#pragma unroll
    for (int i = 0; i < 8; i++) {
        int r = row0 + ty * 8 + i;
        if (r < NN) {
            float4 o0 = make_float4(acc[i][0], acc[i][1], acc[i][2], acc[i][3]);
            float4 o1 = make_float4(acc[i][4], acc[i][5], acc[i][6], acc[i][7]);
            float* dst = &d_PQ[(size_t)r * 256 + half * 128 + tx * 8];
            reinterpret_cast<float4*>(dst)[0] = o0;
            reinterpret_cast<float4*>(dst)[1] = o1;
        }
    }
}

__global__ void k_w0() {
    int j = blockIdx.x;
    int c = threadIdx.x;
    int s = d_src[j];
    int d = d_dst[j];
    float dv = d_dinv[j];
    d_W0[j * CC + c] = (d_PQ[s * 256 + c] + d_PQ[d * 256 + 128 + c]) * dv;
}

// -------------------- fused gather: S1 = sum W0[src], S2(SP) = sum P[src] -----------
__global__ void k_gatherA() {
    const int d = blockIdx.x;
    const int c = threadIdx.x;
    const int p0 = d_start[d], p1 = d_start[d + 1];
    float a0 = 0.f, a1 = 0.f, b0 = 0.f, b1 = 0.f;
    int p = p0;
    for (; p + 2 <= p1; p += 2) {
        int s0 = d_srcs[p], s1 = d_srcs[p + 1];
        a0 += d_W0[s0 * CC + c];
        a1 += d_W0[s1 * CC + c];
        b0 += d_PQ[s0 * 256 + c];
        b1 += d_PQ[s1 * 256 + c];
    }
    if (p < p1) {
        int s0 = d_srcs[p];
        a0 += d_W0[s0 * CC + c];
        b0 += d_PQ[s0 * 256 + c];
    }
    d_S1[d * CC + c] = a0 + a1;
    d_S2[d * CC + c] = b0 + b1;
}

// -------------------- second gather: S2 = sum W0[src]  --------------------
__global__ void k_gatherS2() {
    const int d = blockIdx.x;
    const int c = threadIdx.x;
    const int p0 = d_start[d], p1 = d_start[d + 1];
    float a0 = 0.f, a1 = 0.f, a2 = 0.f, a3 = 0.f;
    int p = p0;
    for (; p + 4 <= p1; p += 4) {
        a0 += d_W0[d_srcs[p] * CC + c];
        a1 += d_W0[d_srcs[p + 1] * CC + c];
        a2 += d_W0[d_srcs[p + 2] * CC + c];
        a3 += d_W0[d_srcs[p + 3] * CC + c];
    }
    for (; p < p1; p++) a0 += d_W0[d_srcs[p] * CC + c];
    d_S2[d * CC + c] = (a0 + a1) + (a2 + a3);
}

// -------------------- BN stats: node algebra + edge-row corrections (fused) ---------
__global__ void k_stats(const float* __restrict__ b1) {
    const int c = threadIdx.x;
    const int n0 = blockIdx.x * 128;
    const float b1c = b1[c];
    float s = 0.f, ss = 0.f;
    for (int i = 0; i < 128; i++) {
        int n = n0 + i;
        if (n < NN) {
            float od = (float)d_ocnt[n];
            float id = (float)d_cnt[n];
            float pv = d_PQ[n * 256 + c];
            float qv = d_PQ[n * 256 + 128 + c] + b1c;
            float sp = d_S2[n * CC + c];
            s += od * pv + id * qv;
            ss += od * pv * pv + id * qv * qv + 2.f * qv * sp;
            int sN = d_src[n], dN = d_dst[n];
            float dv = d_dinv[n];
            float h0 = d_PQ[sN * 256 + c] + d_PQ[dN * 256 + 128 + c];
            float naive = h0 + b1c;
            float tru = fmaf(h0, dv * dv, fmaf(dv, d_S1[n * CC + c], b1c));
            s += tru - naive;
            ss += tru * tru - naive * naive;
        }
    }
    atomicAdd(&d_sum[c], (double)s);
    atomicAdd(&d_sumsq[c], (double)ss);
}

__global__ void k_bnfinal(const float* __restrict__ bn_g, const float* __restrict__ bn_b,
                          const float* __restrict__ b1) {
    int c = threadIdx.x;
    double mu = d_sum[c] / (double)EE;
    double var = d_sumsq[c] / (double)EE - mu * mu;
    float rstd = rsqrtf((float)var + EPSV);
    float a = bn_g[c] * rstd;
    d_bnA[c] = a;
    d_bnB[c] = fmaf(b1[c], a, fmaf(-(float)mu, a, bn_b[c]));
}

// ========== fp32 A-tile builder (for g2small only) ====
__device__ __forceinline__ void build_a_tile(
    float As[16][128], const int* ssrc, const int* sdst, const float* sdv,
    const float* sA, const float* sB, int row0, int m, int kh, int k0) {
    const int s = ssrc[m], d = sdst[m];
    const float dv = sdv[m];
    const float4* pp = reinterpret_cast<const float4*>(&d_PQ[s * 256 + k0 + kh]);
    float4 p0 = pp[0], p1 = pp[1];
    const float4* qp = reinterpret_cast<const float4*>(&d_PQ[d * 256 + 128 + k0 + kh]);
    float4 q0 = qp[0], q1 = qp[1];
    float h[8] = {p0.x + q0.x, p0.y + q0.y, p0.z + q0.z, p0.w + q0.w,
                  p1.x + q1.x, p1.y + q1.y, p1.z + q1.z, p1.w + q1.w};
    if (dv >= 0.f) {
        const float4* s1p = reinterpret_cast<const float4*>(&d_S1[(row0 + m) * CC + k0 + kh]);
        float4 t0 = s1p[0], t1 = s1p[1];
        float sv[8] = {t0.x, t0.y, t0.z, t0.w, t1.x, t1.y, t1.z, t1.w};
        float dv2 = dv * dv;
#pragma unroll
        for (int t = 0; t < 8; t++) h[t] = fmaf(h[t], dv2, dv * sv[t]);
    }
#pragma unroll
    for (int t = 0; t < 8; t++) {
        int kk = k0 + kh + t;
        As[kh + t][m] = fmaxf(fmaf(h[t], sA[kk], sB[kk]), 0.f);
    }
}

// -------------------- g2small (fp32, rows < NN only) --------------------
__global__ __launch_bounds__(256) void k_g2small(const float* __restrict__ W2) {
    __shared__ __align__(16) float As[16][128];
    __shared__ __align__(16) float Bs[16][128];
    __shared__ int ssrc[128], sdst[128];
    __shared__ float sdv[128], sA[128], sB[128];
    const int tid = threadIdx.x;
    const int tx = tid & 15, ty = tid >> 4;
    const int row0 = blockIdx.x * 128;
    const int m = tid & 127;
    const int kh = (tid >> 7) * 8;
    const int kb = tid >> 4;
    const int n0 = (tid & 15) * 8;

    if (tid < 128) {
        int rr = row0 + tid;
        ssrc[tid] = d_src[rr];
        sdst[tid] = d_dst[rr];
        sdv[tid] = (rr < NN) ? d_dinv[rr] : -1.f;
        sA[tid] = d_bnA[tid];
        sB[tid] = d_bnB[tid];
    }
    __syncthreads();

    float acc[8][8];
#pragma unroll
    for (int i = 0; i < 8; i++)
#pragma unroll
        for (int j = 0; j < 8; j++) acc[i][j] = 0.f;

    for (int k0 = 0; k0 < 128; k0 += 16) {
        build_a_tile(As, ssrc, sdst, sdv, sA, sB, row0, m, kh, k0);
        const float4* bp = reinterpret_cast<const float4*>(
            W2 + (size_t)(k0 + kb) * 128 + n0);
        float4 b0 = bp[0], b1v = bp[1];
        *reinterpret_cast<float4*>(&Bs[kb][n0]) = b0;
        *reinterpret_cast<float4*>(&Bs[kb][n0 + 4]) = b1v;
        __syncthreads();
#pragma unroll
        for (int k = 0; k < 16; k++) {
            float a[8], b[8];
            *reinterpret_cast<float4*>(a)     = *reinterpret_cast<const float4*>(&As[k][ty * 8]);
            *reinterpret_cast<float4*>(a + 4) = *reinterpret_cast<const float4*>(&As[k][ty * 8 + 4]);
            *reinterpret_cast<float4*>(b)     = *reinterpret_cast<const float4*>(&Bs[k][tx * 8]);
            *reinterpret_cast<float4*>(b + 4) = *reinterpret_cast<const float4*>(&Bs[k][tx * 8 + 4]);
#pragma unroll
            for (int i = 0; i < 8; i++)
#pragma unroll
                for (int j = 0; j < 8; j++) acc[i][j] = fmaf(a[i], b[j], acc[i][j]);
        }
        __syncthreads();
    }
#pragma unroll
    for (int i = 0; i < 8; i++) {
        int r = row0 + ty * 8 + i;
        if (r < NN) {
            float dv = d_dinv[r];
            float4 o0 = make_float4(acc[i][0] * dv, acc[i][1] * dv, acc[i][2] * dv, acc[i][3] * dv);
            float4 o1 = make_float4(acc[i][4] * dv, acc[i][5] * dv, acc[i][6] * dv, acc[i][7] * dv);
            float* dst = &d_W0[r * CC + tx * 8];
            reinterpret_cast<float4*>(dst)[0] = o0;
            reinterpret_cast<float4*>(dst)[1] = o1;
        }
    }
}

// ====== k_final: producer/consumer, single fp16 A x fp16 B, mma.sync ==========
__device__ __forceinline__ uint32_t su(const void* p) {
    return (uint32_t)__cvta_generic_to_shared(p);
}
__device__ __forceinline__ uint32_t pack2h(float v0, float v1) {
    __half h0 = __float2half_rn(v0), h1 = __float2half_rn(v1);
    return ((uint32_t)__half_as_ushort(h1) << 16) | (uint32_t)__half_as_ushort(h0);
}

#define BARRIER() asm volatile("bar.sync 0;" ::: "memory")

#define LDSM_X4(r0, r1, r2, r3, addr)                                              \
    asm volatile("ldmatrix.sync.aligned.m8n8.x4.shared.b16 {%0,%1,%2,%3},[%4];"    \
                 : "=r"(r0), "=r"(r1), "=r"(r2), "=r"(r3) : "r"(addr))
#define LDSM_X4T(r0, r1, r2, r3, addr)                                                  \
    asm volatile("ldmatrix.sync.aligned.m8n8.x4.trans.shared.b16 {%0,%1,%2,%3},[%4];"   \
                 : "=r"(r0), "=r"(r1), "=r"(r2), "=r"(r3) : "r"(addr))
#define MMAF16(d, a0, a1, a2, a3, b0, b1)                                               \
    asm volatile("mma.sync.aligned.m16n8k16.row.col.f32.f16.f16.f32 "                   \
                 "{%0,%1,%2,%3},{%4,%5,%6,%7},{%8,%9},{%0,%1,%2,%3};"                   \
                 : "+f"(d[0]), "+f"(d[1]), "+f"(d[2]), "+f"(d[3])                       \
                 : "r"(a0), "r"(a1), "r"(a2), "r"(a3), "r"(b0), "r"(b1))

__global__ __launch_bounds__(256, 1) void k_final(const float* __restrict__ b2,
                                                  const float* __restrict__ lng,
                                                  const float* __restrict__ lnb,
                                                  const float* __restrict__ W3,
                                                  const float* __restrict__ b3,
                                                  float* __restrict__ out) {
    extern __shared__ __align__(16) char dynsmem[];
    __half* Bf  = (__half*)dynsmem;
    __half* A0h = Bf + TILEB;            // buffer 0
    __half* A1h = A0h + TILEB;           // buffer 1

    __shared__ float sA[128], sB[128], sb2[128], slg[128], slb[128], sw3[128];

    const int tid = threadIdx.x;
    const int lane = tid & 31;
    const int w = tid >> 5;
    const int base = blockIdx.x * 512;

    if (tid < 128) {
        sA[tid] = d_bnA[tid];
        sB[tid] = d_bnB[tid];
        sb2[tid] = b2[tid];
        slg[tid] = lng[tid];
        slb[tid] = lnb[tid];
        sw3[tid] = W3[tid];
    }
    // copy B fp16 (34,816 B)
    {
        const uint4* gb = reinterpret_cast<const uint4*>(d_Bf);
        uint4* sb = reinterpret_cast<uint4*>(Bf);
        for (int i = tid; i < 2176; i += 256) sb[i] = gb[i];
    }
    BARRIER();   // #0: consts + B ready

    if (w < 4) {
        // ================= producers: 128 threads, one full row each =================
        const int ptid = tid;   // 0..127
        for (int t = 0; t < 4; t++) {
            __half* Ah = (t & 1) ? A1h : A0h;
            const int r = base + t * 128 + ptid;
            const int s = d_src[r], d = d_dst[r];
            const float dv = (r < NN) ? d_dinv[r] : -1.f;
            const float dv2 = dv * dv;
            const float4* pp = reinterpret_cast<const float4*>(&d_PQ[s * 256]);
            const float4* qp = reinterpret_cast<const float4*>(&d_PQ[d * 256 + 128]);
            const float4* s1p = reinterpret_cast<const float4*>(&d_S1[r * CC]);
            uint32_t* ahp = reinterpret_cast<uint32_t*>(&Ah[ptid * ASTRIDE]);
#pragma unroll 8
            for (int i = 0; i < 32; i++) {
                float4 p = pp[i], q = qp[i];
                float h0 = p.x + q.x, h1 = p.y + q.y, h2 = p.z + q.z, h3 = p.w + q.w;
                if (dv >= 0.f) {
                    float4 tt = s1p[i];
                    h0 = fmaf(h0, dv2, dv * tt.x);
                    h1 = fmaf(h1, dv2, dv * tt.y);
                    h2 = fmaf(h2, dv2, dv * tt.z);
                    h3 = fmaf(h3, dv2, dv * tt.w);
                }
                int c = 4 * i;
                float v0 = fmaxf(fmaf(h0, sA[c + 0], sB[c + 0]), 0.f);
                float v1 = fmaxf(fmaf(h1, sA[c + 1], sB[c + 1]), 0.f);
                float v2 = fmaxf(fmaf(h2, sA[c + 2], sB[c + 2]), 0.f);
                float v3 = fmaxf(fmaf(h3, sA[c + 3], sB[c + 3]), 0.f);
                ahp[2 * i]     = pack2h(v0, v1);
                ahp[2 * i + 1] = pack2h(v2, v3);
            }
            BARRIER();   // tile t built
        }
    } else {
        // ================= consumers: warp cw owns rows cw*32..+31, all 128 cols ======
        const int cw = w - 4;
        const int aOffBase = (cw * 32 + (lane & 15)) * ASTRIDE + ((lane >> 4) << 3);
        const int bRowK = (lane & 7) + (((lane >> 3) & 1) << 3);
        const int bColN = (lane >> 4) << 3;
        const uint32_t bFB = su(Bf);
        const int rbase = cw * 32 + (lane >> 2);
        const int cb = (lane & 3) * 2;
        const float inv = 1.f / 128.f;
        const float b3v = b3[0];

        for (int t = 0; t < 4; t++) {
            BARRIER();   // wait tile t built
            const int row0 = base + t * 128;
            const uint32_t aHB = su((t & 1) ? A1h : A0h);

            float acc[2][16][4];
#pragma unroll
            for (int rb = 0; rb < 2; rb++)
#pragma unroll
                for (int i = 0; i < 16; i++)
#pragma unroll
                    for (int j = 0; j < 4; j++) acc[rb][i][j] = 0.f;

            for (int k0 = 0; k0 < 128; k0 += 16) {
                uint32_t a0h0, a0h1, a0h2, a0h3;
                uint32_t a1h0, a1h1, a1h2, a1h3;
                LDSM_X4(a0h0, a0h1, a0h2, a0h3, aHB + 2u * (aOffBase + k0));
                LDSM_X4(a1h0, a1h1, a1h2, a1h3, aHB + 2u * (aOffBase + 16 * ASTRIDE + k0));
                const int bKOff = (bRowK + k0) * ASTRIDE + bColN;
#pragma unroll
                for (int nt2 = 0; nt2 < 8; nt2++) {
                    const int n0 = nt2 * 16;
                    uint32_t bf0, bf1, bf2, bf3;
                    LDSM_X4T(bf0, bf1, bf2, bf3, bFB + 2u * (bKOff + n0));
                    MMAF16(acc[0][2 * nt2],     a0h0, a0h1, a0h2, a0h3, bf0, bf1);
                    MMAF16(acc[0][2 * nt2 + 1], a0h0, a0h1, a0h2, a0h3, bf2, bf3);
                    MMAF16(acc[1][2 * nt2],     a1h0, a1h1, a1h2, a1h3, bf0, bf1);
                    MMAF16(acc[1][2 * nt2 + 1], a1h0, a1h1, a1h2, a1h3, bf2, bf3);
                }
            }

            // ---- epilogue (per-warp; LN reductions within 4-lane groups) ----
#pragma unroll
            for (int rb = 0; rb < 2; rb++) {
#pragma unroll
                for (int sub = 0; sub < 2; sub++) {
                    const int r = rbase + rb * 16 + sub * 8;
                    const int rg = row0 + r;
                    const bool small = (rg < NN);
                    float dv = 1.f, d2 = 1.f;
                    if (small) { dv = d_dinv[rg]; d2 = dv * dv; }
                    float s = 0.f, ss = 0.f;
#pragma unroll
                    for (int nt = 0; nt < 16; nt++) {
                        const int c = cb + nt * 8;
                        float2 sv = make_float2(0.f, 0.f);
                        if (small) sv = *reinterpret_cast<const float2*>(&d_S2[rg * CC + c]);
                        float v0 = fmaf(acc[rb][nt][2 * sub + 0], d2, fmaf(dv, sv.x, sb2[c]));
                        float v1 = fmaf(acc[rb][nt][2 * sub + 1], d2, fmaf(dv, sv.y, sb2[c + 1]));
                        acc[rb][nt][2 * sub + 0] = v0;
                        acc[rb][nt][2 * sub + 1] = v1;
                        s += v0 + v1;
                        ss += v0 * v0 + v1 * v1;
                    }
#pragma unroll
                    for (int o = 1; o <= 2; o <<= 1) {
                        s  += __shfl_xor_sync(0xffffffffu, s,  o);
                        ss += __shfl_xor_sync(0xffffffffu, ss, o);
                    }
                    float mu = s * inv;
                    float rstd = rsqrtf(ss * inv - mu * mu + EPSV);
                    float dot = 0.f;
#pragma unroll
                    for (int nt = 0; nt < 16; nt++) {
                        const int c = cb + nt * 8;
                        float y0 = fmaf((acc[rb][nt][2 * sub + 0] - mu) * rstd, slg[c],     slb[c]);
                        float y1 = fmaf((acc[rb][nt][2 * sub + 1] - mu) * rstd, slg[c + 1], slb[c + 1]);
                        dot = fmaf(fmaxf(y0, 0.f), sw3[c],     dot);
                        dot = fmaf(fmaxf(y1, 0.f), sw3[c + 1], dot);
                    }
#pragma unroll
                    for (int o = 1; o <= 2; o <<= 1)
                        dot += __shfl_xor_sync(0xffffffffu, dot, o);
                    if ((lane & 3) == 0) out[rg] = dot + b3v;
                }
            }
        }
    }
}

// -------------------- launch --------------------
extern "C" void kernel_launch(void* const* d_in, const int* in_sizes, int n_in,
                              void* d_out, int out_size) {
    const float* x    = (const float*)d_in[0];
    const int*   ei32 = (const int*)d_in[1];
    const float* W1   = (const float*)d_in[2];
    const float* b1   = (const float*)d_in[3];
    const float* bn_g = (const float*)d_in[4];
    const float* bn_b = (const float*)d_in[5];
    const float* W2   = (const float*)d_in[6];
    const float* b2   = (const float*)d_in[7];
    const float* ln_g = (const float*)d_in[8];
    const float* ln_b = (const float*)d_in[9];
    const float* W3   = (const float*)d_in[10];
    const float* b3   = (const float*)d_in[11];
    float* out = (float*)d_out;

    const int FIN_SMEM = 3 * TILEB * 2;   // 104,448 B
    cudaFuncSetAttribute(k_final, cudaFuncAttributeMaxDynamicSharedMemorySize, FIN_SMEM);

    k_zero<<<256, 256>>>();
    k_detect<<<1, 32>>>(ei32);
    k_prepw<<<64, 256>>>(W2);
    k_convert<<<1024, 256>>>(ei32);
    k_dinv<<<(NN + 255) / 256, 256>>>();
    k_scan<<<1, 1024>>>();
    k_fill<<<(EE + 255) / 256, 256>>>();
    k_pq<<<dim3((NN + 127) / 128, 2), 256>>>(x, W1);
    k_w0<<<NN, CC>>>();
    k_gatherA<<<NN, CC>>>();               // S1 + SP(S2) in one pass
    k_stats<<<(NN + 127) / 128, CC>>>(b1); // node algebra + edge corrections
    k_bnfinal<<<1, CC>>>(bn_g, bn_b, b1);
    k_g2small<<<(NN + 127) / 128, 256>>>(W2);
    k_gatherS2<<<NN, CC>>>();              // real S2 (overwrites SP)
    k_final<<<EE / 512, 256, FIN_SMEM>>>(b2, ln_g, ln_b, W3, b3, out);
}

// round 15
// speedup vs baseline: 1.3724x; 1.1695x over previous
#include <cuda_runtime.h>
#include <cuda_bf16.h>
#include <cuda_fp16.h>
#include <stdint.h>
#include <math.h>

#define NN 20000
#define EE 640000
#define CC 128
#define EPSV 1e-5f
#define ASTRIDE 136
#define TILEB (128 * ASTRIDE)          // fp16 elements per tile buffer

// -------------------- scratch (device globals; no allocation) --------------------
__device__ __align__(16) float  d_PQ[NN * 256];   // [node][0:128]=P, [128:256]=Q (fp32, preprocessing)
__device__ __align__(16) float  d_W0[NN * CC];
__device__ __align__(16) float  d_S1[NN * CC];
__device__ __align__(16) float  d_S2[NN * CC];    // first SP (stats), later real S2
__device__ __align__(16) __half d_Bf[TILEB];      // W2 fp16, padded rows
__device__ __align__(16) __half d_Ph[NN * CC];    // bnA*P          (5 MB)
__device__ __align__(16) __half d_Qh[NN * CC];    // bnA*Q + bnB    (5 MB)
__device__ int    d_src[EE];
__device__ int    d_dst[EE];
__device__ int    d_is64;
__device__ int    d_cnt[NN];      // indeg
__device__ int    d_ocnt[NN];     // outdeg
__device__ int    d_start[NN + 1];
__device__ int    d_cursor[NN];
__device__ int    d_srcs[EE];
__device__ float  d_dinv[NN];
__device__ double d_sum[CC];
__device__ double d_sumsq[CC];
__device__ float  d_bnA[CC];
__device__ float  d_bnB[CC];

// -------------------- dtype detect --------------------
__global__ void k_detect(const int* __restrict__ ei32) {
    if (threadIdx.x == 0) {
        int orv = 0;
        for (int i = 0; i < 128; i++) orv |= ei32[2 * i + 1];
        d_is64 = (orv == 0) ? 1 : 0;
    }
}

__global__ void k_zero() {
    int i = blockIdx.x * blockDim.x + threadIdx.x;
    int stride = gridDim.x * blockDim.x;
    for (int j = i; j < NN; j += stride) { d_cnt[j] = 0; d_ocnt[j] = 0; }
    if (i < CC) { d_sum[i] = 0.0; d_sumsq[i] = 0.0; }
}

__global__ void k_convert(const int* __restrict__ ei32) {
    const int is64 = d_is64;
    int i = blockIdx.x * blockDim.x + threadIdx.x;
    int stride = gridDim.x * blockDim.x;
    for (int e = i; e < EE; e += stride) {
        int s, d;
        if (is64) { s = ei32[2 * e]; d = ei32[2 * (EE + e)]; }
        else      { s = ei32[e];     d = ei32[EE + e]; }
        d_src[e] = s;
        d_dst[e] = d;
        atomicAdd(&d_cnt[d], 1);
        atomicAdd(&d_ocnt[s], 1);
    }
}

__global__ void k_dinv() {
    int i = blockIdx.x * blockDim.x + threadIdx.x;
    if (i < NN) d_dinv[i] = rsqrtf(1.0f + (float)d_cnt[i]);
}

__global__ void k_scan() {
    __shared__ int sh[1024];
    __shared__ int carry_s;
    const int tid = threadIdx.x;
    if (tid == 0) carry_s = 0;
    __syncthreads();
    for (int base = 0; base < NN; base += 1024) {
        int idx = base + tid;
        int v = (idx < NN) ? d_cnt[idx] : 0;
        sh[tid] = v;
        __syncthreads();
        for (int o = 1; o < 1024; o <<= 1) {
            int t = (tid >= o) ? sh[tid - o] : 0;
            __syncthreads();
            sh[tid] += t;
            __syncthreads();
        }
        int excl = sh[tid] - v + carry_s;
        if (idx < NN) { d_start[idx] = excl; d_cursor[idx] = excl; }
        __syncthreads();
        if (tid == 0) carry_s += sh[1023];
        __syncthreads();
    }
    if (tid == 0) d_start[NN] = carry_s;
}

__global__ void k_fill() {
    int e = blockIdx.x * blockDim.x + threadIdx.x;
    if (e < EE) {
        int d = d_dst[e];
        int pos = atomicAdd(&d_cursor[d], 1);
        d_srcs[pos] = d_src[e];
    }
}

// -------------------- W2 fp16, padded rows --------------------
__global__ void k_prepw(const float* __restrict__ W2) {
    int idx = blockIdx.x * blockDim.x + threadIdx.x;   // 16384
    int k = idx >> 7, n = idx & 127;
    d_Bf[k * ASTRIDE + n] = __float2half_rn(W2[(size_t)k * 128 + n]);
}

// -------------------- fold BN into PQ, store fp16 --------------------
__global__ void k_preph() {
    int n = blockIdx.x;
    int c = threadIdx.x;
    float a = d_bnA[c], b = d_bnB[c];
    d_Ph[n * CC + c] = __float2half_rn(a * d_PQ[n * 256 + c]);
    d_Qh[n * CC + c] = __float2half_rn(fmaf(a, d_PQ[n * 256 + 128 + c], b));
}

// -------------------- PQ = x @ [W1_top | W1_bot] --------------------
__global__ __launch_bounds__(256) void k_pq(const float* __restrict__ x,
                                            const float* __restrict__ W1) {
    __shared__ __align__(16) float As[16][128];
    __shared__ __align__(16) float Bs[16][128];
    const int tid = threadIdx.x;
    const int tx = tid & 15, ty = tid >> 4;
    const int row0 = blockIdx.x * 128;
    const int half = blockIdx.y;
    const int m = tid & 127;
    const int kh = (tid >> 7) * 8;
    const int kb = tid >> 4;
    const int n0 = (tid & 15) * 8;

    float acc[8][8];
#pragma unroll
    for (int i = 0; i < 8; i++)
#pragma unroll
        for (int j = 0; j < 8; j++) acc[i][j] = 0.f;

    for (int k0 = 0; k0 < 128; k0 += 16) {
        float4 a0 = make_float4(0, 0, 0, 0), a1 = make_float4(0, 0, 0, 0);
        int rr = row0 + m;
        if (rr < NN) {
            const float4* ap = reinterpret_cast<const float4*>(x + (size_t)rr * 128 + k0 + kh);
            a0 = ap[0]; a1 = ap[1];
        }
        As[kh + 0][m] = a0.x; As[kh + 1][m] = a0.y; As[kh + 2][m] = a0.z; As[kh + 3][m] = a0.w;
        As[kh + 4][m] = a1.x; As[kh + 5][m] = a1.y; As[kh + 6][m] = a1.z; As[kh + 7][m] = a1.w;

        const float4* bp = reinterpret_cast<const float4*>(
            W1 + (size_t)(half * 128 + k0 + kb) * 128 + n0);
        float4 b0 = bp[0], b1v = bp[1];
        *reinterpret_cast<float4*>(&Bs[kb][n0]) = b0;
        *reinterpret_cast<float4*>(&Bs[kb][n0 + 4]) = b1v;
        __syncthreads();
#pragma unroll
        for (int k = 0; k < 16; k++) {
            float a[8], b[8];
            *reinterpret_cast<float4*>(a)     = *reinterpret_cast<const float4*>(&As[k][ty * 8]);
            *reinterpret_cast<float4*>(a + 4) = *reinterpret_cast<const float4*>(&As[k][ty * 8 + 4]);
            *reinterpret_cast<float4*>(b)     = *reinterpret_cast<const float4*>(&Bs[k][tx * 8]);
            *reinterpret_cast<float4*>(b + 4) = *reinterpret_cast<const float4*>(&Bs[k][tx * 8 + 4]);
#pragma unroll
            for (int i = 0; i < 8; i++)
#pragma unroll
                for (int j = 0; j < 8; j++) acc[i][j] = fmaf(a[i], b[j], acc[i][j]);
        }
        __syncthreads();
    }
#pragma unroll
    for (int i = 0; i < 8; i++) {
        int r = row0 + ty * 8 + i;
        if (r < NN) {
            float4 o0 = make_float4(acc[i][0], acc[i][1], acc[i][2], acc[i][3]);
            float4 o1 = make_float4(acc[i][4], acc[i][5], acc[i][6], acc[i][7]);
            float* dst = &d_PQ[(size_t)r * 256 + half * 128 + tx * 8];
            reinterpret_cast<float4*>(dst)[0] = o0;
            reinterpret_cast<float4*>(dst)[1] = o1;
        }
    }
}

__global__ void k_w0() {
    int j = blockIdx.x;
    int c = threadIdx.x;
    int s = d_src[j];
    int d = d_dst[j];
    float dv = d_dinv[j];
    d_W0[j * CC + c] = (d_PQ[s * 256 + c] + d_PQ[d * 256 + 128 + c]) * dv;
}

// -------------------- fused gather: S1 = sum W0[src], S2(SP) = sum P[src] -----------
__global__ void k_gatherA() {
    const int d = blockIdx.x;
    const int c = threadIdx.x;
    const int p0 = d_start[d], p1 = d_start[d + 1];
    float a0 = 0.f, a1 = 0.f, b0 = 0.f, b1 = 0.f;
    int p = p0;
    for (; p + 2 <= p1; p += 2) {
        int s0 = d_srcs[p], s1 = d_srcs[p + 1];
        a0 += d_W0[s0 * CC + c];
        a1 += d_W0[s1 * CC + c];
        b0 += d_PQ[s0 * 256 + c];
        b1 += d_PQ[s1 * 256 + c];
    }
    if (p < p1) {
        int s0 = d_srcs[p];
        a0 += d_W0[s0 * CC + c];
        b0 += d_PQ[s0 * 256 + c];
    }
    d_S1[d * CC + c] = a0 + a1;
    d_S2[d * CC + c] = b0 + b1;
}

// -------------------- second gather: S2 = sum W0[src]  --------------------
__global__ void k_gatherS2() {
    const int d = blockIdx.x;
    const int c = threadIdx.x;
    const int p0 = d_start[d], p1 = d_start[d + 1];
    float a0 = 0.f, a1 = 0.f, a2 = 0.f, a3 = 0.f;
    int p = p0;
    for (; p + 4 <= p1; p += 4) {
        a0 += d_W0[d_srcs[p] * CC + c];
        a1 += d_W0[d_srcs[p + 1] * CC + c];
        a2 += d_W0[d_srcs[p + 2] * CC + c];
        a3 += d_W0[d_srcs[p + 3] * CC + c];
    }
    for (; p < p1; p++) a0 += d_W0[d_srcs[p] * CC + c];
    d_S2[d * CC + c] = (a0 + a1) + (a2 + a3);
}

// -------------------- BN stats: node algebra + edge-row corrections (fused) ---------
__global__ void k_stats(const float* __restrict__ b1) {
    const int c = threadIdx.x;
    const int n0 = blockIdx.x * 128;
    const float b1c = b1[c];
    float s = 0.f, ss = 0.f;
    for (int i = 0; i < 128; i++) {
        int n = n0 + i;
        if (n < NN) {
            float od = (float)d_ocnt[n];
            float id = (float)d_cnt[n];
            float pv = d_PQ[n * 256 + c];
            float qv = d_PQ[n * 256 + 128 + c] + b1c;
            float sp = d_S2[n * CC + c];
            s += od * pv + id * qv;
            ss += od * pv * pv + id * qv * qv + 2.f * qv * sp;
            int sN = d_src[n], dN = d_dst[n];
            float dv = d_dinv[n];
            float h0 = d_PQ[sN * 256 + c] + d_PQ[dN * 256 + 128 + c];
            float naive = h0 + b1c;
            float tru = fmaf(h0, dv * dv, fmaf(dv, d_S1[n * CC + c], b1c));
            s += tru - naive;
            ss += tru * tru - naive * naive;
        }
    }
    atomicAdd(&d_sum[c], (double)s);
    atomicAdd(&d_sumsq[c], (double)ss);
}

__global__ void k_bnfinal(const float* __restrict__ bn_g, const float* __restrict__ bn_b,
                          const float* __restrict__ b1) {
    int c = threadIdx.x;
    double mu = d_sum[c] / (double)EE;
    double var = d_sumsq[c] / (double)EE - mu * mu;
    float rstd = rsqrtf((float)var + EPSV);
    float a = bn_g[c] * rstd;
    d_bnA[c] = a;
    d_bnB[c] = fmaf(b1[c], a, fmaf(-(float)mu, a, bn_b[c]));
}

// ========== fp32 A-tile builder (for g2small only) ====
__device__ __forceinline__ void build_a_tile(
    float As[16][128], const int* ssrc, const int* sdst, const float* sdv,
    const float* sA, const float* sB, int row0, int m, int kh, int k0) {
    const int s = ssrc[m], d = sdst[m];
    const float dv = sdv[m];
    const float4* pp = reinterpret_cast<const float4*>(&d_PQ[s * 256 + k0 + kh]);
    float4 p0 = pp[0], p1 = pp[1];
    const float4* qp = reinterpret_cast<const float4*>(&d_PQ[d * 256 + 128 + k0 + kh]);
    float4 q0 = qp[0], q1 = qp[1];
    float h[8] = {p0.x + q0.x, p0.y + q0.y, p0.z + q0.z, p0.w + q0.w,
                  p1.x + q1.x, p1.y + q1.y, p1.z + q1.z, p1.w + q1.w};
    if (dv >= 0.f) {
        const float4* s1p = reinterpret_cast<const float4*>(&d_S1[(row0 + m) * CC + k0 + kh]);
        float4 t0 = s1p[0], t1 = s1p[1];
        float sv[8] = {t0.x, t0.y, t0.z, t0.w, t1.x, t1.y, t1.z, t1.w};
        float dv2 = dv * dv;
#pragma unroll
        for (int t = 0; t < 8; t++) h[t] = fmaf(h[t], dv2, dv * sv[t]);
    }
#pragma unroll
    for (int t = 0; t < 8; t++) {
        int kk = k0 + kh + t;
        As[kh + t][m] = fmaxf(fmaf(h[t], sA[kk], sB[kk]), 0.f);
    }
}

// -------------------- g2small (fp32, rows < NN only) --------------------
__global__ __launch_bounds__(256) void k_g2small(const float* __restrict__ W2) {
    __shared__ __align__(16) float As[16][128];
    __shared__ __align__(16) float Bs[16][128];
    __shared__ int ssrc[128], sdst[128];
    __shared__ float sdv[128], sA[128], sB[128];
    const int tid = threadIdx.x;
    const int tx = tid & 15, ty = tid >> 4;
    const int row0 = blockIdx.x * 128;
    const int m = tid & 127;
    const int kh = (tid >> 7) * 8;
    const int kb = tid >> 4;
    const int n0 = (tid & 15) * 8;

    if (tid < 128) {
        int rr = row0 + tid;
        ssrc[tid] = d_src[rr];
        sdst[tid] = d_dst[rr];
        sdv[tid] = (rr < NN) ? d_dinv[rr] : -1.f;
        sA[tid] = d_bnA[tid];
        sB[tid] = d_bnB[tid];
    }
    __syncthreads();

    float acc[8][8];
#pragma unroll
    for (int i = 0; i < 8; i++)
#pragma unroll
        for (int j = 0; j < 8; j++) acc[i][j] = 0.f;

    for (int k0 = 0; k0 < 128; k0 += 16) {
        build_a_tile(As, ssrc, sdst, sdv, sA, sB, row0, m, kh, k0);
        const float4* bp = reinterpret_cast<const float4*>(
            W2 + (size_t)(k0 + kb) * 128 + n0);
        float4 b0 = bp[0], b1v = bp[1];
        *reinterpret_cast<float4*>(&Bs[kb][n0]) = b0;
        *reinterpret_cast<float4*>(&Bs[kb][n0 + 4]) = b1v;
        __syncthreads();
#pragma unroll
        for (int k = 0; k < 16; k++) {
            float a[8], b[8];
            *reinterpret_cast<float4*>(a)     = *reinterpret_cast<const float4*>(&As[k][ty * 8]);
            *reinterpret_cast<float4*>(a + 4) = *reinterpret_cast<const float4*>(&As[k][ty * 8 + 4]);
            *reinterpret_cast<float4*>(b)     = *reinterpret_cast<const float4*>(&Bs[k][tx * 8]);
            *reinterpret_cast<float4*>(b + 4) = *reinterpret_cast<const float4*>(&Bs[k][tx * 8 + 4]);
#pragma unroll
            for (int i = 0; i < 8; i++)
#pragma unroll
                for (int j = 0; j < 8; j++) acc[i][j] = fmaf(a[i], b[j], acc[i][j]);
        }
        __syncthreads();
    }
#pragma unroll
    for (int i = 0; i < 8; i++) {
        int r = row0 + ty * 8 + i;
        if (r < NN) {
            float dv = d_dinv[r];
            float4 o0 = make_float4(acc[i][0] * dv, acc[i][1] * dv, acc[i][2] * dv, acc[i][3] * dv);
            float4 o1 = make_float4(acc[i][4] * dv, acc[i][5] * dv, acc[i][6] * dv, acc[i][7] * dv);
            float* dst = &d_W0[r * CC + tx * 8];
            reinterpret_cast<float4*>(dst)[0] = o0;
            reinterpret_cast<float4*>(dst)[1] = o1;
        }
    }
}

// ====== k_final: producer/consumer, single fp16 A x fp16 B, mma.sync ==========
__device__ __forceinline__ uint32_t su(const void* p) {
    return (uint32_t)__cvta_generic_to_shared(p);
}
__device__ __forceinline__ uint32_t pack2h(float v0, float v1) {
    __half h0 = __float2half_rn(v0), h1 = __float2half_rn(v1);
    return ((uint32_t)__half_as_ushort(h1) << 16) | (uint32_t)__half_as_ushort(h0);
}
__device__ __forceinline__ uint32_t hadd_relu2(uint32_t a, uint32_t b) {
    __half2 va = *reinterpret_cast<__half2*>(&a);
    __half2 vb = *reinterpret_cast<__half2*>(&b);
    __half2 r = __hmax2(__hadd2(va, vb), __half2(__float2half_rn(0.f), __float2half_rn(0.f)));
    return *reinterpret_cast<uint32_t*>(&r);
}

#define BARRIER() asm volatile("bar.sync 0;" ::: "memory")

#define LDSM_X4(r0, r1, r2, r3, addr)                                              \
    asm volatile("ldmatrix.sync.aligned.m8n8.x4.shared.b16 {%0,%1,%2,%3},[%4];"    \
                 : "=r"(r0), "=r"(r1), "=r"(r2), "=r"(r3) : "r"(addr))
#define LDSM_X4T(r0, r1, r2, r3, addr)                                                  \
    asm volatile("ldmatrix.sync.aligned.m8n8.x4.trans.shared.b16 {%0,%1,%2,%3},[%4];"   \
                 : "=r"(r0), "=r"(r1), "=r"(r2), "=r"(r3) : "r"(addr))
#define MMAF16(d, a0, a1, a2, a3, b0, b1)                                               \
    asm volatile("mma.sync.aligned.m16n8k16.row.col.f32.f16.f16.f32 "                   \
                 "{%0,%1,%2,%3},{%4,%5,%6,%7},{%8,%9},{%0,%1,%2,%3};"                   \
                 : "+f"(d[0]), "+f"(d[1]), "+f"(d[2]), "+f"(d[3])                       \
                 : "r"(a0), "r"(a1), "r"(a2), "r"(a3), "r"(b0), "r"(b1))

__global__ __launch_bounds__(256, 1) void k_final(const float* __restrict__ b2,
                                                  const float* __restrict__ lng,
                                                  const float* __restrict__ lnb,
                                                  const float* __restrict__ W3,
                                                  const float* __restrict__ b3,
                                                  float* __restrict__ out) {
    extern __shared__ __align__(16) char dynsmem[];
    __half* Bf  = (__half*)dynsmem;
    __half* A0h = Bf + TILEB;            // buffer 0
    __half* A1h = A0h + TILEB;           // buffer 1

    __shared__ float sA[128], sB[128], sb2[128], slg[128], slb[128], sw3[128];

    const int tid = threadIdx.x;
    const int lane = tid & 31;
    const int w = tid >> 5;
    const int base = blockIdx.x * 512;

    if (tid < 128) {
        sA[tid] = d_bnA[tid];
        sB[tid] = d_bnB[tid];
        sb2[tid] = b2[tid];
        slg[tid] = lng[tid];
        slb[tid] = lnb[tid];
        sw3[tid] = W3[tid];
    }
    // copy B fp16 (34,816 B)
    {
        const uint4* gb = reinterpret_cast<const uint4*>(d_Bf);
        uint4* sb = reinterpret_cast<uint4*>(Bf);
        for (int i = tid; i < 2176; i += 256) sb[i] = gb[i];
    }
    BARRIER();   // #0: consts + B ready

    if (w < 4) {
        // ================= producers: 128 threads, one full row each =================
        const int ptid = tid;   // 0..127
        for (int t = 0; t < 4; t++) {
            __half* Ah = (t & 1) ? A1h : A0h;
            const int r = base + t * 128 + ptid;
            const int s = d_src[r], d = d_dst[r];
            uint32_t* ahp = reinterpret_cast<uint32_t*>(&Ah[ptid * ASTRIDE]);
            if (r >= NN) {
                // fast path: Ah = relu(P'[s] + Q'[d]) in fp16
                const uint4* pp = reinterpret_cast<const uint4*>(&d_Ph[s * CC]);
                const uint4* qp = reinterpret_cast<const uint4*>(&d_Qh[d * CC]);
#pragma unroll 4
                for (int i = 0; i < 16; i++) {
                    uint4 a = pp[i], b = qp[i];
                    uint4 o;
                    o.x = hadd_relu2(a.x, b.x);
                    o.y = hadd_relu2(a.y, b.y);
                    o.z = hadd_relu2(a.z, b.z);
                    o.w = hadd_relu2(a.w, b.w);
                    reinterpret_cast<uint4*>(ahp)[i] = o;
                }
            } else {
                // GCN-corrected fp32 path (first NN edge rows only)
                const float dv = d_dinv[r];
                const float dv2 = dv * dv;
                const float4* pp = reinterpret_cast<const float4*>(&d_PQ[s * 256]);
                const float4* qp = reinterpret_cast<const float4*>(&d_PQ[d * 256 + 128]);
                const float4* s1p = reinterpret_cast<const float4*>(&d_S1[r * CC]);
#pragma unroll 8
                for (int i = 0; i < 32; i++) {
                    float4 p = pp[i], q = qp[i];
                    float4 tt = s1p[i];
                    float h0 = fmaf(p.x + q.x, dv2, dv * tt.x);
                    float h1 = fmaf(p.y + q.y, dv2, dv * tt.y);
                    float h2 = fmaf(p.z + q.z, dv2, dv * tt.z);
                    float h3 = fmaf(p.w + q.w, dv2, dv * tt.w);
                    int c = 4 * i;
                    float v0 = fmaxf(fmaf(h0, sA[c + 0], sB[c + 0]), 0.f);
                    float v1 = fmaxf(fmaf(h1, sA[c + 1], sB[c + 1]), 0.f);
                    float v2 = fmaxf(fmaf(h2, sA[c + 2], sB[c + 2]), 0.f);
                    float v3 = fmaxf(fmaf(h3, sA[c + 3], sB[c + 3]), 0.f);
                    ahp[2 * i]     = pack2h(v0, v1);
                    ahp[2 * i + 1] = pack2h(v2, v3);
                }
            }
            BARRIER();   // tile t built
        }
    } else {
        // ================= consumers: warp cw owns rows cw*32..+31, all 128 cols ======
        const int cw = w - 4;
        const int aOffBase = (cw * 32 + (lane & 15)) * ASTRIDE + ((lane >> 4) << 3);
        const int bRowK = (lane & 7) + (((lane >> 3) & 1) << 3);
        const int bColN = (lane >> 4) << 3;
        const uint32_t bFB = su(Bf);
        const int rbase = cw * 32 + (lane >> 2);
        const int cb = (lane & 3) * 2;
        const float inv = 1.f / 128.f;
        const float b3v = b3[0];

        for (int t = 0; t < 4; t++) {
            BARRIER();   // wait tile t built
            const int row0 = base + t * 128;
            const uint32_t aHB = su((t & 1) ? A1h : A0h);

            float acc[2][16][4];
#pragma unroll
            for (int rb = 0; rb < 2; rb++)
#pragma unroll
                for (int i = 0; i < 16; i++)
#pragma unroll
                    for (int j = 0; j < 4; j++) acc[rb][i][j] = 0.f;

            for (int k0 = 0; k0 < 128; k0 += 16) {
                uint32_t a0h0, a0h1, a0h2, a0h3;
                uint32_t a1h0, a1h1, a1h2, a1h3;
                LDSM_X4(a0h0, a0h1, a0h2, a0h3, aHB + 2u * (aOffBase + k0));
                LDSM_X4(a1h0, a1h1, a1h2, a1h3, aHB + 2u * (aOffBase + 16 * ASTRIDE + k0));
                const int bKOff = (bRowK + k0) * ASTRIDE + bColN;
#pragma unroll
                for (int nt2 = 0; nt2 < 8; nt2++) {
                    const int n0 = nt2 * 16;
                    uint32_t bf0, bf1, bf2, bf3;
                    LDSM_X4T(bf0, bf1, bf2, bf3, bFB + 2u * (bKOff + n0));
                    MMAF16(acc[0][2 * nt2],     a0h0, a0h1, a0h2, a0h3, bf0, bf1);
                    MMAF16(acc[0][2 * nt2 + 1], a0h0, a0h1, a0h2, a0h3, bf2, bf3);
                    MMAF16(acc[1][2 * nt2],     a1h0, a1h1, a1h2, a1h3, bf0, bf1);
                    MMAF16(acc[1][2 * nt2 + 1], a1h0, a1h1, a1h2, a1h3, bf2, bf3);
                }
            }

            // ---- epilogue (per-warp; LN reductions within 4-lane groups) ----
#pragma unroll
            for (int rb = 0; rb < 2; rb++) {
#pragma unroll
                for (int sub = 0; sub < 2; sub++) {
                    const int r = rbase + rb * 16 + sub * 8;
                    const int rg = row0 + r;
                    const bool small = (rg < NN);
                    float dv = 1.f, d2 = 1.f;
                    if (small) { dv = d_dinv[rg]; d2 = dv * dv; }
                    float s = 0.f, ss = 0.f;
#pragma unroll
                    for (int nt = 0; nt < 16; nt++) {
                        const int c = cb + nt * 8;
                        float2 sv = make_float2(0.f, 0.f);
                        if (small) sv = *reinterpret_cast<const float2*>(&d_S2[rg * CC + c]);
                        float v0 = fmaf(acc[rb][nt][2 * sub + 0], d2, fmaf(dv, sv.x, sb2[c]));
                        float v1 = fmaf(acc[rb][nt][2 * sub + 1], d2, fmaf(dv, sv.y, sb2[c + 1]));
                        acc[rb][nt][2 * sub + 0] = v0;
                        acc[rb][nt][2 * sub + 1] = v1;
                        s += v0 + v1;
                        ss += v0 * v0 + v1 * v1;
                    }
#pragma unroll
                    for (int o = 1; o <= 2; o <<= 1) {
                        s  += __shfl_xor_sync(0xffffffffu, s,  o);
                        ss += __shfl_xor_sync(0xffffffffu, ss, o);
                    }
                    float mu = s * inv;
                    float rstd = rsqrtf(ss * inv - mu * mu + EPSV);
                    float dot = 0.f;
#pragma unroll
                    for (int nt = 0; nt < 16; nt++) {
                        const int c = cb + nt * 8;
                        float y0 = fmaf((acc[rb][nt][2 * sub + 0] - mu) * rstd, slg[c],     slb[c]);
                        float y1 = fmaf((acc[rb][nt][2 * sub + 1] - mu) * rstd, slg[c + 1], slb[c + 1]);
                        dot = fmaf(fmaxf(y0, 0.f), sw3[c],     dot);
                        dot = fmaf(fmaxf(y1, 0.f), sw3[c + 1], dot);
                    }
#pragma unroll
                    for (int o = 1; o <= 2; o <<= 1)
                        dot += __shfl_xor_sync(0xffffffffu, dot, o);
                    if ((lane & 3) == 0) out[rg] = dot + b3v;
                }
            }
        }
    }
}

// -------------------- launch --------------------
extern "C" void kernel_launch(void* const* d_in, const int* in_sizes, int n_in,
                              void* d_out, int out_size) {
    const float* x    = (const float*)d_in[0];
    const int*   ei32 = (const int*)d_in[1];
    const float* W1   = (const float*)d_in[2];
    const float* b1   = (const float*)d_in[3];
    const float* bn_g = (const float*)d_in[4];
    const float* bn_b = (const float*)d_in[5];
    const float* W2   = (const float*)d_in[6];
    const float* b2   = (const float*)d_in[7];
    const float* ln_g = (const float*)d_in[8];
    const float* ln_b = (const float*)d_in[9];
    const float* W3   = (const float*)d_in[10];
    const float* b3   = (const float*)d_in[11];
    float* out = (float*)d_out;

    const int FIN_SMEM = 3 * TILEB * 2;   // 104,448 B
    cudaFuncSetAttribute(k_final, cudaFuncAttributeMaxDynamicSharedMemorySize, FIN_SMEM);

    k_zero<<<256, 256>>>();
    k_detect<<<1, 32>>>(ei32);
    k_prepw<<<64, 256>>>(W2);
    k_convert<<<1024, 256>>>(ei32);
    k_dinv<<<(NN + 255) / 256, 256>>>();
    k_scan<<<1, 1024>>>();
    k_fill<<<(EE + 255) / 256, 256>>>();
    k_pq<<<dim3((NN + 127) / 128, 2), 256>>>(x, W1);
    k_w0<<<NN, CC>>>();
    k_gatherA<<<NN, CC>>>();               // S1 + SP(S2) in one pass
    k_stats<<<(NN + 127) / 128, CC>>>(b1); // node algebra + edge corrections
    k_bnfinal<<<1, CC>>>(bn_g, bn_b, b1);
    k_preph<<<NN, CC>>>();                 // fold BN into PQ, fp16
    k_g2small<<<(NN + 127) / 128, 256>>>(W2);
    k_gatherS2<<<NN, CC>>>();              // real S2 (overwrites SP)
    k_final<<<EE / 512, 256, FIN_SMEM>>>(b2, ln_g, ln_b, W3, b3, out);
}

// round 16
// speedup vs baseline: 1.3768x; 1.0032x over previous
#include <cuda_runtime.h>
#include <cuda_bf16.h>
#include <cuda_fp16.h>
#include <stdint.h>
#include <math.h>

#define NN 20000
#define EE 640000
#define CC 128
#define EPSV 1e-5f
#define ASTRIDE 136
#define TILEB (128 * ASTRIDE)          // fp16 elements per tile buffer

// -------------------- scratch (device globals; no allocation) --------------------
__device__ __align__(16) float  d_PQ[NN * 256];   // [node][0:128]=P, [128:256]=Q (fp32)
__device__ __align__(16) __half d_W0h[NN * CC];   // fp16 gather payload (5 MB)
__device__ __align__(16) __half d_Pr[NN * CC];    // raw P fp16 (for SP stats gather)
__device__ __align__(16) float  d_S1[NN * CC];
__device__ __align__(16) float  d_S2[NN * CC];    // first SP (stats), later real S2
__device__ __align__(16) __half d_Bf[TILEB];      // W2 fp16, padded rows
__device__ __align__(16) __half d_Ph[NN * CC];    // bnA*P          (5 MB)
__device__ __align__(16) __half d_Qh[NN * CC];    // bnA*Q + bnB    (5 MB)
__device__ int    d_src[EE];
__device__ int    d_dst[EE];
__device__ int    d_is64;
__device__ int    d_cnt[NN];      // indeg
__device__ int    d_ocnt[NN];     // outdeg
__device__ int    d_start[NN + 1];
__device__ int    d_cursor[NN];
__device__ int    d_srcs[EE];
__device__ float  d_dinv[NN];
__device__ double d_sum[CC];
__device__ double d_sumsq[CC];
__device__ float  d_bnA[CC];
__device__ float  d_bnB[CC];

// -------------------- dtype detect --------------------
__global__ void k_detect(const int* __restrict__ ei32) {
    if (threadIdx.x == 0) {
        int orv = 0;
        for (int i = 0; i < 128; i++) orv |= ei32[2 * i + 1];
        d_is64 = (orv == 0) ? 1 : 0;
    }
}

__global__ void k_zero() {
    int i = blockIdx.x * blockDim.x + threadIdx.x;
    int stride = gridDim.x * blockDim.x;
    for (int j = i; j < NN; j += stride) { d_cnt[j] = 0; d_ocnt[j] = 0; }
    if (i < CC) { d_sum[i] = 0.0; d_sumsq[i] = 0.0; }
}

__global__ void k_convert(const int* __restrict__ ei32) {
    const int is64 = d_is64;
    int i = blockIdx.x * blockDim.x + threadIdx.x;
    int stride = gridDim.x * blockDim.x;
    for (int e = i; e < EE; e += stride) {
        int s, d;
        if (is64) { s = ei32[2 * e]; d = ei32[2 * (EE + e)]; }
        else      { s = ei32[e];     d = ei32[EE + e]; }
        d_src[e] = s;
        d_dst[e] = d;
        atomicAdd(&d_cnt[d], 1);
        atomicAdd(&d_ocnt[s], 1);
    }
}

__global__ void k_dinv() {
    int i = blockIdx.x * blockDim.x + threadIdx.x;
    if (i < NN) d_dinv[i] = rsqrtf(1.0f + (float)d_cnt[i]);
}

__global__ void k_scan() {
    __shared__ int sh[1024];
    __shared__ int carry_s;
    const int tid = threadIdx.x;
    if (tid == 0) carry_s = 0;
    __syncthreads();
    for (int base = 0; base < NN; base += 1024) {
        int idx = base + tid;
        int v = (idx < NN) ? d_cnt[idx] : 0;
        sh[tid] = v;
        __syncthreads();
        for (int o = 1; o < 1024; o <<= 1) {
            int t = (tid >= o) ? sh[tid - o] : 0;
            __syncthreads();
            sh[tid] += t;
            __syncthreads();
        }
        int excl = sh[tid] - v + carry_s;
        if (idx < NN) { d_start[idx] = excl; d_cursor[idx] = excl; }
        __syncthreads();
        if (tid == 0) carry_s += sh[1023];
        __syncthreads();
    }
    if (tid == 0) d_start[NN] = carry_s;
}

__global__ void k_fill() {
    int e = blockIdx.x * blockDim.x + threadIdx.x;
    if (e < EE) {
        int d = d_dst[e];
        int pos = atomicAdd(&d_cursor[d], 1);
        d_srcs[pos] = d_src[e];
    }
}

// -------------------- W2 fp16, padded rows --------------------
__global__ void k_prepw(const float* __restrict__ W2) {
    int idx = blockIdx.x * blockDim.x + threadIdx.x;   // 16384
    int k = idx >> 7, n = idx & 127;
    d_Bf[k * ASTRIDE + n] = __float2half_rn(W2[(size_t)k * 128 + n]);
}

// -------------------- fold BN into PQ, store fp16 --------------------
__global__ void k_preph() {
    int n = blockIdx.x;
    int c = threadIdx.x;
    float a = d_bnA[c], b = d_bnB[c];
    d_Ph[n * CC + c] = __float2half_rn(a * d_PQ[n * 256 + c]);
    d_Qh[n * CC + c] = __float2half_rn(fmaf(a, d_PQ[n * 256 + 128 + c], b));
}

// -------------------- PQ = x @ [W1_top | W1_bot] (+ fp16 raw P copy) ----------------
__global__ __launch_bounds__(256) void k_pq(const float* __restrict__ x,
                                            const float* __restrict__ W1) {
    __shared__ __align__(16) float As[16][128];
    __shared__ __align__(16) float Bs[16][128];
    const int tid = threadIdx.x;
    const int tx = tid & 15, ty = tid >> 4;
    const int row0 = blockIdx.x * 128;
    const int half = blockIdx.y;
    const int m = tid & 127;
    const int kh = (tid >> 7) * 8;
    const int kb = tid >> 4;
    const int n0 = (tid & 15) * 8;

    float acc[8][8];
#pragma unroll
    for (int i = 0; i < 8; i++)
#pragma unroll
        for (int j = 0; j < 8; j++) acc[i][j] = 0.f;

    for (int k0 = 0; k0 < 128; k0 += 16) {
        float4 a0 = make_float4(0, 0, 0, 0), a1 = make_float4(0, 0, 0, 0);
        int rr = row0 + m;
        if (rr < NN) {
            const float4* ap = reinterpret_cast<const float4*>(x + (size_t)rr * 128 + k0 + kh);
            a0 = ap[0]; a1 = ap[1];
        }
        As[kh + 0][m] = a0.x; As[kh + 1][m] = a0.y; As[kh + 2][m] = a0.z; As[kh + 3][m] = a0.w;
        As[kh + 4][m] = a1.x; As[kh + 5][m] = a1.y; As[kh + 6][m] = a1.z; As[kh + 7][m] = a1.w;

        const float4* bp = reinterpret_cast<const float4*>(
            W1 + (size_t)(half * 128 + k0 + kb) * 128 + n0);
        float4 b0 = bp[0], b1v = bp[1];
        *reinterpret_cast<float4*>(&Bs[kb][n0]) = b0;
        *reinterpret_cast<float4*>(&Bs[kb][n0 + 4]) = b1v;
        __syncthreads();
#pragma unroll
        for (int k = 0; k < 16; k++) {
            float a[8], b[8];
            *reinterpret_cast<float4*>(a)     = *reinterpret_cast<const float4*>(&As[k][ty * 8]);
            *reinterpret_cast<float4*>(a + 4) = *reinterpret_cast<const float4*>(&As[k][ty * 8 + 4]);
            *reinterpret_cast<float4*>(b)     = *reinterpret_cast<const float4*>(&Bs[k][tx * 8]);
            *reinterpret_cast<float4*>(b + 4) = *reinterpret_cast<const float4*>(&Bs[k][tx * 8 + 4]);
#pragma unroll
            for (int i = 0; i < 8; i++)
#pragma unroll
                for (int j = 0; j < 8; j++) acc[i][j] = fmaf(a[i], b[j], acc[i][j]);
        }
        __syncthreads();
    }
#pragma unroll
    for (int i = 0; i < 8; i++) {
        int r = row0 + ty * 8 + i;
        if (r < NN) {
            float4 o0 = make_float4(acc[i][0], acc[i][1], acc[i][2], acc[i][3]);
            float4 o1 = make_float4(acc[i][4], acc[i][5], acc[i][6], acc[i][7]);
            float* dst = &d_PQ[(size_t)r * 256 + half * 128 + tx * 8];
            reinterpret_cast<float4*>(dst)[0] = o0;
            reinterpret_cast<float4*>(dst)[1] = o1;
            if (half == 0) {
                __half hv[8];
#pragma unroll
                for (int j = 0; j < 8; j++) hv[j] = __float2half_rn(acc[i][j]);
                *reinterpret_cast<uint4*>(&d_Pr[r * CC + tx * 8]) =
                    *reinterpret_cast<const uint4*>(hv);
            }
        }
    }
}

// -------------------- W0h[j] = fp16((P+Q)*dinv), j<NN --------------------
__global__ void k_w0() {
    int j = blockIdx.x;
    int c = threadIdx.x;
    int s = d_src[j];
    int d = d_dst[j];
    float dv = d_dinv[j];
    d_W0h[j * CC + c] = __float2half_rn((d_PQ[s * 256 + c] + d_PQ[d * 256 + 128 + c]) * dv);
}

// -------------------- fused gather: S1 = sum W0h[src], S2(SP) = sum Pr[src] ---------
__global__ void k_gatherA() {
    const int d = blockIdx.x;
    const int c = threadIdx.x;
    const int p0 = d_start[d], p1 = d_start[d + 1];
    float a0 = 0.f, a1 = 0.f, b0 = 0.f, b1 = 0.f;
    int p = p0;
    for (; p + 2 <= p1; p += 2) {
        int s0 = d_srcs[p], s1 = d_srcs[p + 1];
        a0 += __half2float(d_W0h[s0 * CC + c]);
        a1 += __half2float(d_W0h[s1 * CC + c]);
        b0 += __half2float(d_Pr[s0 * CC + c]);
        b1 += __half2float(d_Pr[s1 * CC + c]);
    }
    if (p < p1) {
        int s0 = d_srcs[p];
        a0 += __half2float(d_W0h[s0 * CC + c]);
        b0 += __half2float(d_Pr[s0 * CC + c]);
    }
    d_S1[d * CC + c] = a0 + a1;
    d_S2[d * CC + c] = b0 + b1;
}

// -------------------- second gather: S2 = sum W0h[src]  --------------------
__global__ void k_gatherS2() {
    const int d = blockIdx.x;
    const int c = threadIdx.x;
    const int p0 = d_start[d], p1 = d_start[d + 1];
    float a0 = 0.f, a1 = 0.f, a2 = 0.f, a3 = 0.f;
    int p = p0;
    for (; p + 4 <= p1; p += 4) {
        a0 += __half2float(d_W0h[d_srcs[p] * CC + c]);
        a1 += __half2float(d_W0h[d_srcs[p + 1] * CC + c]);
        a2 += __half2float(d_W0h[d_srcs[p + 2] * CC + c]);
        a3 += __half2float(d_W0h[d_srcs[p + 3] * CC + c]);
    }
    for (; p < p1; p++) a0 += __half2float(d_W0h[d_srcs[p] * CC + c]);
    d_S2[d * CC + c] = (a0 + a1) + (a2 + a3);
}

// -------------------- BN stats: node algebra + edge-row corrections (fused) ---------
__global__ void k_stats(const float* __restrict__ b1) {
    const int c = threadIdx.x;
    const int n0 = blockIdx.x * 128;
    const float b1c = b1[c];
    float s = 0.f, ss = 0.f;
    for (int i = 0; i < 128; i++) {
        int n = n0 + i;
        if (n < NN) {
            float od = (float)d_ocnt[n];
            float id = (float)d_cnt[n];
            float pv = d_PQ[n * 256 + c];
            float qv = d_PQ[n * 256 + 128 + c] + b1c;
            float sp = d_S2[n * CC + c];
            s += od * pv + id * qv;
            ss += od * pv * pv + id * qv * qv + 2.f * qv * sp;
            int sN = d_src[n], dN = d_dst[n];
            float dv = d_dinv[n];
            float h0 = d_PQ[sN * 256 + c] + d_PQ[dN * 256 + 128 + c];
            float naive = h0 + b1c;
            float tru = fmaf(h0, dv * dv, fmaf(dv, d_S1[n * CC + c], b1c));
            s += tru - naive;
            ss += tru * tru - naive * naive;
        }
    }
    atomicAdd(&d_sum[c], (double)s);
    atomicAdd(&d_sumsq[c], (double)ss);
}

__global__ void k_bnfinal(const float* __restrict__ bn_g, const float* __restrict__ bn_b,
                          const float* __restrict__ b1) {
    int c = threadIdx.x;
    double mu = d_sum[c] / (double)EE;
    double var = d_sumsq[c] / (double)EE - mu * mu;
    float rstd = rsqrtf((float)var + EPSV);
    float a = bn_g[c] * rstd;
    d_bnA[c] = a;
    d_bnB[c] = fmaf(b1[c], a, fmaf(-(float)mu, a, bn_b[c]));
}

// ========== fp32 A-tile builder (for g2small only) ====
__device__ __forceinline__ void build_a_tile(
    float As[16][128], const int* ssrc, const int* sdst, const float* sdv,
    const float* sA, const float* sB, int row0, int m, int kh, int k0) {
    const int s = ssrc[m], d = sdst[m];
    const float dv = sdv[m];
    const float4* pp = reinterpret_cast<const float4*>(&d_PQ[s * 256 + k0 + kh]);
    float4 p0 = pp[0], p1 = pp[1];
    const float4* qp = reinterpret_cast<const float4*>(&d_PQ[d * 256 + 128 + k0 + kh]);
    float4 q0 = qp[0], q1 = qp[1];
    float h[8] = {p0.x + q0.x, p0.y + q0.y, p0.z + q0.z, p0.w + q0.w,
                  p1.x + q1.x, p1.y + q1.y, p1.z + q1.z, p1.w + q1.w};
    if (dv >= 0.f) {
        const float4* s1p = reinterpret_cast<const float4*>(&d_S1[(row0 + m) * CC + k0 + kh]);
        float4 t0 = s1p[0], t1 = s1p[1];
        float sv[8] = {t0.x, t0.y, t0.z, t0.w, t1.x, t1.y, t1.z, t1.w};
        float dv2 = dv * dv;
#pragma unroll
        for (int t = 0; t < 8; t++) h[t] = fmaf(h[t], dv2, dv * sv[t]);
    }
#pragma unroll
    for (int t = 0; t < 8; t++) {
        int kk = k0 + kh + t;
        As[kh + t][m] = fmaxf(fmaf(h[t], sA[kk], sB[kk]), 0.f);
    }
}

// -------------------- g2small (fp32 math, fp16 output; rows < NN only) ---------------
__global__ __launch_bounds__(256) void k_g2small(const float* __restrict__ W2) {
    __shared__ __align__(16) float As[16][128];
    __shared__ __align__(16) float Bs[16][128];
    __shared__ int ssrc[128], sdst[128];
    __shared__ float sdv[128], sA[128], sB[128];
    const int tid = threadIdx.x;
    const int tx = tid & 15, ty = tid >> 4;
    const int row0 = blockIdx.x * 128;
    const int m = tid & 127;
    const int kh = (tid >> 7) * 8;
    const int kb = tid >> 4;
    const int n0 = (tid & 15) * 8;

    if (tid < 128) {
        int rr = row0 + tid;
        ssrc[tid] = d_src[rr];
        sdst[tid] = d_dst[rr];
        sdv[tid] = (rr < NN) ? d_dinv[rr] : -1.f;
        sA[tid] = d_bnA[tid];
        sB[tid] = d_bnB[tid];
    }
    __syncthreads();

    float acc[8][8];
#pragma unroll
    for (int i = 0; i < 8; i++)
#pragma unroll
        for (int j = 0; j < 8; j++) acc[i][j] = 0.f;

    for (int k0 = 0; k0 < 128; k0 += 16) {
        build_a_tile(As, ssrc, sdst, sdv, sA, sB, row0, m, kh, k0);
        const float4* bp = reinterpret_cast<const float4*>(
            W2 + (size_t)(k0 + kb) * 128 + n0);
        float4 b0 = bp[0], b1v = bp[1];
        *reinterpret_cast<float4*>(&Bs[kb][n0]) = b0;
        *reinterpret_cast<float4*>(&Bs[kb][n0 + 4]) = b1v;
        __syncthreads();
#pragma unroll
        for (int k = 0; k < 16; k++) {
            float a[8], b[8];
            *reinterpret_cast<float4*>(a)     = *reinterpret_cast<const float4*>(&As[k][ty * 8]);
            *reinterpret_cast<float4*>(a + 4) = *reinterpret_cast<const float4*>(&As[k][ty * 8 + 4]);
            *reinterpret_cast<float4*>(b)     = *reinterpret_cast<const float4*>(&Bs[k][tx * 8]);
            *reinterpret_cast<float4*>(b + 4) = *reinterpret_cast<const float4*>(&Bs[k][tx * 8 + 4]);
#pragma unroll
            for (int i = 0; i < 8; i++)
#pragma unroll
                for (int j = 0; j < 8; j++) acc[i][j] = fmaf(a[i], b[j], acc[i][j]);
        }
        __syncthreads();
    }
#pragma unroll
    for (int i = 0; i < 8; i++) {
        int r = row0 + ty * 8 + i;
        if (r < NN) {
            float dv = d_dinv[r];
            __half hv[8];
#pragma unroll
            for (int j = 0; j < 8; j++) hv[j] = __float2half_rn(acc[i][j] * dv);
            *reinterpret_cast<uint4*>(&d_W0h[r * CC + tx * 8]) =
                *reinterpret_cast<const uint4*>(hv);
        }
    }
}

// ====== k_final: producer/consumer, single fp16 A x fp16 B, mma.sync ==========
__device__ __forceinline__ uint32_t su(const void* p) {
    return (uint32_t)__cvta_generic_to_shared(p);
}
__device__ __forceinline__ uint32_t pack2h(float v0, float v1) {
    __half h0 = __float2half_rn(v0), h1 = __float2half_rn(v1);
    return ((uint32_t)__half_as_ushort(h1) << 16) | (uint32_t)__half_as_ushort(h0);
}
__device__ __forceinline__ uint32_t hadd_relu2(uint32_t a, uint32_t b) {
    __half2 va = *reinterpret_cast<__half2*>(&a);
    __half2 vb = *reinterpret_cast<__half2*>(&b);
    __half2 r = __hmax2(__hadd2(va, vb), __half2(__float2half_rn(0.f), __float2half_rn(0.f)));
    return *reinterpret_cast<uint32_t*>(&r);
}

#define BARRIER() asm volatile("bar.sync 0;" ::: "memory")

#define LDSM_X4(r0, r1, r2, r3, addr)                                              \
    asm volatile("ldmatrix.sync.aligned.m8n8.x4.shared.b16 {%0,%1,%2,%3},[%4];"    \
                 : "=r"(r0), "=r"(r1), "=r"(r2), "=r"(r3) : "r"(addr))
#define LDSM_X4T(r0, r1, r2, r3, addr)                                                  \
    asm volatile("ldmatrix.sync.aligned.m8n8.x4.trans.shared.b16 {%0,%1,%2,%3},[%4];"   \
                 : "=r"(r0), "=r"(r1), "=r"(r2), "=r"(r3) : "r"(addr))
#define MMAF16(d, a0, a1, a2, a3, b0, b1)                                               \
    asm volatile("mma.sync.aligned.m16n8k16.row.col.f32.f16.f16.f32 "                   \
                 "{%0,%1,%2,%3},{%4,%5,%6,%7},{%8,%9},{%0,%1,%2,%3};"                   \
                 : "+f"(d[0]), "+f"(d[1]), "+f"(d[2]), "+f"(d[3])                       \
                 : "r"(a0), "r"(a1), "r"(a2), "r"(a3), "r"(b0), "r"(b1))

__global__ __launch_bounds__(256, 1) void k_final(const float* __restrict__ b2,
                                                  const float* __restrict__ lng,
                                                  const float* __restrict__ lnb,
                                                  const float* __restrict__ W3,
                                                  const float* __restrict__ b3,
                                                  float* __restrict__ out) {
    extern __shared__ __align__(16) char dynsmem[];
    __half* Bf  = (__half*)dynsmem;
    __half* A0h = Bf + TILEB;            // buffer 0
    __half* A1h = A0h + TILEB;           // buffer 1

    __shared__ float sA[128], sB[128], sb2[128], slg[128], slb[128], sw3[128];

    const int tid = threadIdx.x;
    const int lane = tid & 31;
    const int w = tid >> 5;
    const int base = blockIdx.x * 512;

    if (tid < 128) {
        sA[tid] = d_bnA[tid];
        sB[tid] = d_bnB[tid];
        sb2[tid] = b2[tid];
        slg[tid] = lng[tid];
        slb[tid] = lnb[tid];
        sw3[tid] = W3[tid];
    }
    // copy B fp16 (34,816 B)
    {
        const uint4* gb = reinterpret_cast<const uint4*>(d_Bf);
        uint4* sb = reinterpret_cast<uint4*>(Bf);
        for (int i = tid; i < 2176; i += 256) sb[i] = gb[i];
    }
    BARRIER();   // #0: consts + B ready

    if (w < 4) {
        // ================= producers: 128 threads, one full row each =================
        const int ptid = tid;   // 0..127
        for (int t = 0; t < 4; t++) {
            __half* Ah = (t & 1) ? A1h : A0h;
            const int r = base + t * 128 + ptid;
            const int s = d_src[r], d = d_dst[r];
            uint32_t* ahp = reinterpret_cast<uint32_t*>(&Ah[ptid * ASTRIDE]);
            if (r >= NN) {
                const uint4* pp = reinterpret_cast<const uint4*>(&d_Ph[s * CC]);
                const uint4* qp = reinterpret_cast<const uint4*>(&d_Qh[d * CC]);
#pragma unroll 4
                for (int i = 0; i < 16; i++) {
                    uint4 a = pp[i], b = qp[i];
                    uint4 o;
                    o.x = hadd_relu2(a.x, b.x);
                    o.y = hadd_relu2(a.y, b.y);
                    o.z = hadd_relu2(a.z, b.z);
                    o.w = hadd_relu2(a.w, b.w);
                    reinterpret_cast<uint4*>(ahp)[i] = o;
                }
            } else {
                const float dv = d_dinv[r];
                const float dv2 = dv * dv;
                const float4* pp = reinterpret_cast<const float4*>(&d_PQ[s * 256]);
                const float4* qp = reinterpret_cast<const float4*>(&d_PQ[d * 256 + 128]);
                const float4* s1p = reinterpret_cast<const float4*>(&d_S1[r * CC]);
#pragma unroll 8
                for (int i = 0; i < 32; i++) {
                    float4 p = pp[i], q = qp[i];
                    float4 tt = s1p[i];
                    float h0 = fmaf(p.x + q.x, dv2, dv * tt.x);
                    float h1 = fmaf(p.y + q.y, dv2, dv * tt.y);
                    float h2 = fmaf(p.z + q.z, dv2, dv * tt.z);
                    float h3 = fmaf(p.w + q.w, dv2, dv * tt.w);
                    int c = 4 * i;
                    float v0 = fmaxf(fmaf(h0, sA[c + 0], sB[c + 0]), 0.f);
                    float v1 = fmaxf(fmaf(h1, sA[c + 1], sB[c + 1]), 0.f);
                    float v2 = fmaxf(fmaf(h2, sA[c + 2], sB[c + 2]), 0.f);
                    float v3 = fmaxf(fmaf(h3, sA[c + 3], sB[c + 3]), 0.f);
                    ahp[2 * i]     = pack2h(v0, v1);
                    ahp[2 * i + 1] = pack2h(v2, v3);
                }
            }
            BARRIER();   // tile t built
        }
    } else {
        // ================= consumers: warp cw owns rows cw*32..+31, all 128 cols ======
        const int cw = w - 4;
        const int aOffBase = (cw * 32 + (lane & 15)) * ASTRIDE + ((lane >> 4) << 3);
        const int bRowK = (lane & 7) + (((lane >> 3) & 1) << 3);
        const int bColN = (lane >> 4) << 3;
        const uint32_t bFB = su(Bf);
        const int rbase = cw * 32 + (lane >> 2);
        const int cb = (lane & 3) * 2;
        const float inv = 1.f / 128.f;
        const float b3v = b3[0];

        for (int t = 0; t < 4; t++) {
            BARRIER();   // wait tile t built
            const int row0 = base + t * 128;
            const uint32_t aHB = su((t & 1) ? A1h : A0h);

            float acc[2][16][4];
#pragma unroll
            for (int rb = 0; rb < 2; rb++)
#pragma unroll
                for (int i = 0; i < 16; i++)
#pragma unroll
                    for (int j = 0; j < 4; j++) acc[rb][i][j] = 0.f;

            for (int k0 = 0; k0 < 128; k0 += 16) {
                uint32_t a0h0, a0h1, a0h2, a0h3;
                uint32_t a1h0, a1h1, a1h2, a1h3;
                LDSM_X4(a0h0, a0h1, a0h2, a0h3, aHB + 2u * (aOffBase + k0));
                LDSM_X4(a1h0, a1h1, a1h2, a1h3, aHB + 2u * (aOffBase + 16 * ASTRIDE + k0));
                const int bKOff = (bRowK + k0) * ASTRIDE + bColN;
#pragma unroll
                for (int nt2 = 0; nt2 < 8; nt2++) {
                    const int n0 = nt2 * 16;
                    uint32_t bf0, bf1, bf2, bf3;
                    LDSM_X4T(bf0, bf1, bf2, bf3, bFB + 2u * (bKOff + n0));
                    MMAF16(acc[0][2 * nt2],     a0h0, a0h1, a0h2, a0h3, bf0, bf1);
                    MMAF16(acc[0][2 * nt2 + 1], a0h0, a0h1, a0h2, a0h3, bf2, bf3);
                    MMAF16(acc[1][2 * nt2],     a1h0, a1h1, a1h2, a1h3, bf0, bf1);
                    MMAF16(acc[1][2 * nt2 + 1], a1h0, a1h1, a1h2, a1h3, bf2, bf3);
                }
            }

            // ---- epilogue (per-warp; LN reductions within 4-lane groups) ----
#pragma unroll
            for (int rb = 0; rb < 2; rb++) {
#pragma unroll
                for (int sub = 0; sub < 2; sub++) {
                    const int r = rbase + rb * 16 + sub * 8;
                    const int rg = row0 + r;
                    const bool small = (rg < NN);
                    float dv = 1.f, d2 = 1.f;
                    if (small) { dv = d_dinv[rg]; d2 = dv * dv; }
                    float s = 0.f, ss = 0.f;
#pragma unroll
                    for (int nt = 0; nt < 16; nt++) {
                        const int c = cb + nt * 8;
                        float2 sv = make_float2(0.f, 0.f);
                        if (small) sv = *reinterpret_cast<const float2*>(&d_S2[rg * CC + c]);
                        float v0 = fmaf(acc[rb][nt][2 * sub + 0], d2, fmaf(dv, sv.x, sb2[c]));
                        float v1 = fmaf(acc[rb][nt][2 * sub + 1], d2, fmaf(dv, sv.y, sb2[c + 1]));
                        acc[rb][nt][2 * sub + 0] = v0;
                        acc[rb][nt][2 * sub + 1] = v1;
                        s += v0 + v1;
                        ss += v0 * v0 + v1 * v1;
                    }
#pragma unroll
                    for (int o = 1; o <= 2; o <<= 1) {
                        s  += __shfl_xor_sync(0xffffffffu, s,  o);
                        ss += __shfl_xor_sync(0xffffffffu, ss, o);
                    }
                    float mu = s * inv;
                    float rstd = rsqrtf(ss * inv - mu * mu + EPSV);
                    float dot = 0.f;
#pragma unroll
                    for (int nt = 0; nt < 16; nt++) {
                        const int c = cb + nt * 8;
                        float y0 = fmaf((acc[rb][nt][2 * sub + 0] - mu) * rstd, slg[c],     slb[c]);
                        float y1 = fmaf((acc[rb][nt][2 * sub + 1] - mu) * rstd, slg[c + 1], slb[c + 1]);
                        dot = fmaf(fmaxf(y0, 0.f), sw3[c],     dot);
                        dot = fmaf(fmaxf(y1, 0.f), sw3[c + 1], dot);
                    }
#pragma unroll
                    for (int o = 1; o <= 2; o <<= 1)
                        dot += __shfl_xor_sync(0xffffffffu, dot, o);
                    if ((lane & 3) == 0) out[rg] = dot + b3v;
                }
            }
        }
    }
}

// -------------------- launch --------------------
extern "C" void kernel_launch(void* const* d_in, const int* in_sizes, int n_in,
                              void* d_out, int out_size) {
    const float* x    = (const float*)d_in[0];
    const int*   ei32 = (const int*)d_in[1];
    const float* W1   = (const float*)d_in[2];
    const float* b1   = (const float*)d_in[3];
    const float* bn_g = (const float*)d_in[4];
    const float* bn_b = (const float*)d_in[5];
    const float* W2   = (const float*)d_in[6];
    const float* b2   = (const float*)d_in[7];
    const float* ln_g = (const float*)d_in[8];
    const float* ln_b = (const float*)d_in[9];
    const float* W3   = (const float*)d_in[10];
    const float* b3   = (const float*)d_in[11];
    float* out = (float*)d_out;

    const int FIN_SMEM = 3 * TILEB * 2;   // 104,448 B
    cudaFuncSetAttribute(k_final, cudaFuncAttributeMaxDynamicSharedMemorySize, FIN_SMEM);

    k_zero<<<256, 256>>>();
    k_detect<<<1, 32>>>(ei32);
    k_prepw<<<64, 256>>>(W2);
    k_convert<<<1024, 256>>>(ei32);
    k_dinv<<<(NN + 255) / 256, 256>>>();
    k_scan<<<1, 1024>>>();
    k_fill<<<(EE + 255) / 256, 256>>>();
    k_pq<<<dim3((NN + 127) / 128, 2), 256>>>(x, W1);
    k_w0<<<NN, CC>>>();
    k_gatherA<<<NN, CC>>>();               // S1 + SP(S2) in one pass (fp16 payloads)
    k_stats<<<(NN + 127) / 128, CC>>>(b1); // node algebra + edge corrections
    k_bnfinal<<<1, CC>>>(bn_g, bn_b, b1);
    k_preph<<<NN, CC>>>();                 // fold BN into PQ, fp16
    k_g2small<<<(NN + 127) / 128, 256>>>(W2);
    k_gatherS2<<<NN, CC>>>();              // real S2 (fp16 payload)
    k_final<<<EE / 512, 256, FIN_SMEM>>>(b2, ln_g, ln_b, W3, b3, out);
}